// round 1
// baseline (speedup 1.0000x reference)
#include <cuda_runtime.h>
#include <cuda_bf16.h>
#include <math.h>

// Problem constants
#define Bz 2
#define Tz 2048
#define Cz 1024
#define Hh 16
#define Dd 64
#define CH 512
#define NT (Bz*Tz)          // 4096 rows

// ---------------- scratch (device globals; no runtime alloc) ----------------
__device__ float g_Himp[NT*CH];
__device__ float g_xi[NT*Cz];
__device__ float g_Hrsn[NT*Cz];
__device__ float g_reasoned[NT*Cz];
__device__ float g_Q[NT*Cz];
__device__ float g_K[NT*Cz];
__device__ float g_V[NT*Cz];
__device__ float g_attn[NT*Cz];
__device__ float g_proj[NT*Cz];
__device__ float g_part[16*Cz];
__device__ float g_rmean[Bz*Cz];
__device__ float g_temp[Bz*Hh];

// ---------------- helpers ----------------
__device__ __forceinline__ float blockReduceSum(float v) {
    __shared__ float sh[32];
    int lane = threadIdx.x & 31, wid = threadIdx.x >> 5;
    #pragma unroll
    for (int o = 16; o; o >>= 1) v += __shfl_down_sync(0xffffffffu, v, o);
    if (lane == 0) sh[wid] = v;
    __syncthreads();
    int nw = blockDim.x >> 5;
    v = (threadIdx.x < nw) ? sh[threadIdx.x] : 0.f;
    if (wid == 0) {
        #pragma unroll
        for (int o = 16; o; o >>= 1) v += __shfl_down_sync(0xffffffffu, v, o);
        if (lane == 0) sh[0] = v;
    }
    __syncthreads();
    float r = sh[0];
    __syncthreads();
    return r;
}

__device__ __forceinline__ float gelu_exact(float x) {
    return 0.5f * x * (1.0f + erff(x * 0.70710678118654752f));
}

// ---------------- SGEMM: C = A[M,K] @ W[K,N] + bias[N] ----------------
// BM=BN=128, BK=8, 256 threads, 8x8 microtile. M,N,K all divisible by tile dims.
#define GBM 128
#define GBN 128
#define GBK 8
__global__ __launch_bounds__(256) void sgemm_bias(
    const float* __restrict__ A, const float* __restrict__ W,
    const float* __restrict__ bias, float* __restrict__ C,
    int M, int N, int K)
{
    __shared__ float As[GBK][GBM];
    __shared__ float Bs[GBK][GBN];
    const int tid = threadIdx.x;
    const int tx = tid & 15;        // 0..15 (N dir)
    const int ty = tid >> 4;        // 0..15 (M dir)
    const int bx = blockIdx.x;      // N tile
    const int by = blockIdx.y;      // M tile

    const float* Ap = A + (size_t)by * GBM * K;
    const float* Wp = W + (size_t)bx * GBN;

    const int arow = tid >> 1;           // 0..127
    const int acol = (tid & 1) * 4;      // 0 or 4
    const int brow = tid >> 5;           // 0..7
    const int bcol = (tid & 31) * 4;     // 0..124

    float acc[8][8];
    #pragma unroll
    for (int i = 0; i < 8; i++)
        #pragma unroll
        for (int j = 0; j < 8; j++) acc[i][j] = 0.f;

    for (int k0 = 0; k0 < K; k0 += GBK) {
        float4 av = *(const float4*)(Ap + (size_t)arow * K + k0 + acol);
        As[acol + 0][arow] = av.x;
        As[acol + 1][arow] = av.y;
        As[acol + 2][arow] = av.z;
        As[acol + 3][arow] = av.w;
        float4 bv = *(const float4*)(Wp + (size_t)(k0 + brow) * N + bcol);
        *(float4*)&Bs[brow][bcol] = bv;
        __syncthreads();
        #pragma unroll
        for (int k = 0; k < GBK; k++) {
            float ra[8], rb[8];
            #pragma unroll
            for (int i = 0; i < 8; i += 4) {
                float4 t = *(const float4*)&As[k][ty * 8 + i];
                ra[i] = t.x; ra[i+1] = t.y; ra[i+2] = t.z; ra[i+3] = t.w;
            }
            #pragma unroll
            for (int j = 0; j < 8; j += 4) {
                float4 t = *(const float4*)&Bs[k][tx * 8 + j];
                rb[j] = t.x; rb[j+1] = t.y; rb[j+2] = t.z; rb[j+3] = t.w;
            }
            #pragma unroll
            for (int i = 0; i < 8; i++)
                #pragma unroll
                for (int j = 0; j < 8; j++)
                    acc[i][j] = fmaf(ra[i], rb[j], acc[i][j]);
        }
        __syncthreads();
    }

    #pragma unroll
    for (int i = 0; i < 8; i++) {
        int row = by * GBM + ty * 8 + i;
        #pragma unroll
        for (int j = 0; j < 8; j += 4) {
            int col = bx * GBN + tx * 8 + j;
            float4 o;
            o.x = acc[i][j + 0] + bias[col + 0];
            o.y = acc[i][j + 1] + bias[col + 1];
            o.z = acc[i][j + 2] + bias[col + 2];
            o.w = acc[i][j + 3] + bias[col + 3];
            *(float4*)&C[(size_t)row * N + col] = o;
        }
    }
}

// ---------------- in-place LayerNorm + GELU over rows ----------------
template<int COLS>
__global__ __launch_bounds__(256) void ln_gelu_kernel(
    float* __restrict__ X, const float* __restrict__ g, const float* __restrict__ beta)
{
    const int row = blockIdx.x;
    float* xr = X + (size_t)row * COLS;
    constexpr int PT = COLS / 256;
    float v[PT];
    float s = 0.f;
    #pragma unroll
    for (int i = 0; i < PT; i++) { v[i] = xr[threadIdx.x + i * 256]; s += v[i]; }
    float mean = blockReduceSum(s) * (1.0f / COLS);
    float s2 = 0.f;
    #pragma unroll
    for (int i = 0; i < PT; i++) { float d = v[i] - mean; s2 += d * d; }
    float var = blockReduceSum(s2) * (1.0f / COLS);
    float rstd = rsqrtf(var + 1e-5f);
    #pragma unroll
    for (int i = 0; i < PT; i++) {
        int c = threadIdx.x + i * 256;
        float y = (v[i] - mean) * rstd * g[c] + beta[c];
        xr[c] = gelu_exact(y);
    }
}

// ---------------- importance gate: imp = max(sigmoid(H@w2+b2),1e-6); xi = x*imp ----------------
__global__ __launch_bounds__(256) void gate_xi_kernel(
    const float* __restrict__ H, const float* __restrict__ w2, const float* __restrict__ b2,
    const float* __restrict__ x, float* __restrict__ xi)
{
    const int row = blockIdx.x;
    float p = 0.f;
    const float* hr = H + (size_t)row * CH;
    for (int c = threadIdx.x; c < CH; c += 256) p += hr[c] * w2[c];
    float sum = blockReduceSum(p);
    float sg = 1.0f / (1.0f + expf(-(sum + b2[0])));
    float imp = fmaxf(sg, 1e-6f);
    const float* xr = x + (size_t)row * Cz;
    float* xo = xi + (size_t)row * Cz;
    for (int c = threadIdx.x; c < Cz; c += 256) xo[c] = xr[c] * imp;
}

// ---------------- column mean over T (two stage, deterministic) ----------------
__global__ void colmean_part(const float* __restrict__ R, float* __restrict__ part) {
    int c = blockIdx.x * 256 + threadIdx.x;     // grid.x = 4
    int b = blockIdx.y;
    int ch = blockIdx.z;                        // 8 chunks of 256
    float s = 0.f;
    int t0 = ch * 256;
    for (int t = t0; t < t0 + 256; t++)
        s += R[((size_t)(b * Tz + t)) * Cz + c];
    part[(ch * Bz + b) * Cz + c] = s;
}
__global__ void colmean_fin(const float* __restrict__ part, float* __restrict__ out) {
    int c = blockIdx.x * 256 + threadIdx.x;
    int b = blockIdx.y;
    float s = 0.f;
    for (int ch = 0; ch < 8; ch++) s += part[(ch * Bz + b) * Cz + c];
    out[b * Cz + c] = s * (1.0f / Tz);
}

// ---------------- temperature net: [B,C] -> [B,H] ----------------
__global__ __launch_bounds__(512) void temp_kernel(
    const float* __restrict__ rmean,
    const float* __restrict__ w1, const float* __restrict__ b1,
    const float* __restrict__ g, const float* __restrict__ beta,
    const float* __restrict__ w2, const float* __restrict__ b2,
    float* __restrict__ temp)
{
    const int b = blockIdx.x;
    const int tid = threadIdx.x;          // 512 threads, one per CH element
    __shared__ float hsm[CH];
    const float* xr = rmean + b * Cz;
    float acc = b1[tid];
    for (int k = 0; k < Cz; k++) acc = fmaf(xr[k], w1[k * CH + tid], acc);
    float mean = blockReduceSum(acc) * (1.0f / CH);
    float d = acc - mean;
    float var = blockReduceSum(d * d) * (1.0f / CH);
    float rstd = rsqrtf(var + 1e-5f);
    float y = d * rstd * g[tid] + beta[tid];
    hsm[tid] = gelu_exact(y);
    __syncthreads();
    if (tid < Hh) {
        float a2 = b2[tid];
        for (int k = 0; k < CH; k++) a2 = fmaf(hsm[k], w2[k * Hh + tid], a2);
        float sp = (a2 > 20.f) ? a2 : log1pf(expf(a2));
        temp[b * Hh + tid] = sp + 0.5f;
    }
}

// ---------------- flash attention ----------------
// grid (T/128, H, B), 128 threads; each thread owns one query row.
#define FBQ 128
#define FBK 64
__global__ __launch_bounds__(128) void flash_attn_kernel(
    const float* __restrict__ Q, const float* __restrict__ Kp,
    const float* __restrict__ Vp, const int* __restrict__ mask,
    const float* __restrict__ temp, float* __restrict__ O)
{
    __shared__ float Ks[FBK][Dd];
    __shared__ float Vs[FBK][Dd];
    __shared__ unsigned char Ms[FBQ][FBK];

    const int b = blockIdx.z, h = blockIdx.y, qt = blockIdx.x;
    const int tid = threadIdx.x;
    const int qi = qt * FBQ + tid;
    const float sc = 0.125f * temp[b * Hh + h];

    float q[Dd];
    const float* qrow = Q + ((size_t)(b * Tz + qi)) * Cz + h * Dd;
    #pragma unroll
    for (int dd = 0; dd < Dd; dd += 4) {
        float4 t = *(const float4*)(qrow + dd);
        q[dd] = t.x; q[dd+1] = t.y; q[dd+2] = t.z; q[dd+3] = t.w;
    }

    float m = -1e30f, l = 0.f;
    float acc[Dd];
    #pragma unroll
    for (int dd = 0; dd < Dd; dd++) acc[dd] = 0.f;

    const int* mbase = mask + ((size_t)b * Tz + (size_t)qt * FBQ) * Tz;

    for (int k0 = 0; k0 < Tz; k0 += FBK) {
        // stage K, V tiles (coalesced float4)
        #pragma unroll
        for (int i = tid; i < FBK * (Dd / 4); i += FBQ) {
            int r = i >> 4, c4 = (i & 15) * 4;
            size_t goff = ((size_t)(b * Tz + k0 + r)) * Cz + h * Dd + c4;
            *(float4*)&Ks[r][c4] = *(const float4*)(Kp + goff);
            *(float4*)&Vs[r][c4] = *(const float4*)(Vp + goff);
        }
        // stage mask tile (coalesced int4 -> uchar)
        #pragma unroll
        for (int i = tid; i < FBQ * (FBK / 4); i += FBQ) {
            int r = i >> 4, c4 = (i & 15) * 4;
            int4 mv = *(const int4*)(mbase + (size_t)r * Tz + k0 + c4);
            Ms[r][c4 + 0] = mv.x ? 1 : 0;
            Ms[r][c4 + 1] = mv.y ? 1 : 0;
            Ms[r][c4 + 2] = mv.z ? 1 : 0;
            Ms[r][c4 + 3] = mv.w ? 1 : 0;
        }
        __syncthreads();

        #pragma unroll 1
        for (int j0 = 0; j0 < FBK; j0 += 16) {
            float s[16];
            #pragma unroll
            for (int j = 0; j < 16; j++) {
                float a = 0.f;
                #pragma unroll
                for (int dd = 0; dd < Dd; dd += 4) {
                    float4 kv = *(const float4*)&Ks[j0 + j][dd];
                    a = fmaf(q[dd], kv.x, a);
                    a = fmaf(q[dd+1], kv.y, a);
                    a = fmaf(q[dd+2], kv.z, a);
                    a = fmaf(q[dd+3], kv.w, a);
                }
                s[j] = Ms[tid][j0 + j] ? a * sc : -1e30f;
            }
            float cm = s[0];
            #pragma unroll
            for (int j = 1; j < 16; j++) cm = fmaxf(cm, s[j]);
            float mnew = fmaxf(m, cm);
            float corr = __expf(m - mnew);
            l *= corr;
            #pragma unroll
            for (int dd = 0; dd < Dd; dd++) acc[dd] *= corr;
            #pragma unroll
            for (int j = 0; j < 16; j++) {
                float p = __expf(s[j] - mnew);
                l += p;
                #pragma unroll
                for (int dd = 0; dd < Dd; dd += 4) {
                    float4 vv = *(const float4*)&Vs[j0 + j][dd];
                    acc[dd]   = fmaf(p, vv.x, acc[dd]);
                    acc[dd+1] = fmaf(p, vv.y, acc[dd+1]);
                    acc[dd+2] = fmaf(p, vv.z, acc[dd+2]);
                    acc[dd+3] = fmaf(p, vv.w, acc[dd+3]);
                }
            }
            m = mnew;
        }
        __syncthreads();
    }

    float inv = 1.0f / l;
    float* orow = O + ((size_t)(b * Tz + qi)) * Cz + h * Dd;
    #pragma unroll
    for (int dd = 0; dd < Dd; dd += 4) {
        float4 o;
        o.x = acc[dd] * inv; o.y = acc[dd+1] * inv;
        o.z = acc[dd+2] * inv; o.w = acc[dd+3] * inv;
        *(float4*)(orow + dd) = o;
    }
}

// ---------------- residual + LayerNorm epilogue ----------------
__global__ __launch_bounds__(256) void resid_ln_kernel(
    const float* __restrict__ x, const float* __restrict__ p,
    const float* __restrict__ g, const float* __restrict__ beta,
    float* __restrict__ out)
{
    const int row = blockIdx.x;
    const float* xr = x + (size_t)row * Cz;
    const float* pr = p + (size_t)row * Cz;
    float v[4];
    float s = 0.f;
    #pragma unroll
    for (int i = 0; i < 4; i++) {
        int c = threadIdx.x + i * 256;
        v[i] = xr[c] + pr[c];
        s += v[i];
    }
    float mean = blockReduceSum(s) * (1.0f / Cz);
    float s2 = 0.f;
    #pragma unroll
    for (int i = 0; i < 4; i++) { float d = v[i] - mean; s2 += d * d; }
    float var = blockReduceSum(s2) * (1.0f / Cz);
    float rstd = rsqrtf(var + 1e-5f);
    #pragma unroll
    for (int i = 0; i < 4; i++) {
        int c = threadIdx.x + i * 256;
        out[(size_t)row * Cz + c] = (v[i] - mean) * rstd * g[c] + beta[c];
    }
}

// ---------------- launch ----------------
extern "C" void kernel_launch(void* const* d_in, const int* in_sizes, int n_in,
                              void* d_out, int out_size)
{
    const float* x      = (const float*)d_in[0];
    const int*   amask  = (const int*)  d_in[1];
    const float* imp_w1 = (const float*)d_in[2];
    const float* imp_b1 = (const float*)d_in[3];
    const float* imp_g  = (const float*)d_in[4];
    const float* imp_be = (const float*)d_in[5];
    const float* imp_w2 = (const float*)d_in[6];
    const float* imp_b2 = (const float*)d_in[7];
    const float* rsn_w1 = (const float*)d_in[8];
    const float* rsn_b1 = (const float*)d_in[9];
    const float* rsn_g  = (const float*)d_in[10];
    const float* rsn_be = (const float*)d_in[11];
    const float* rsn_w2 = (const float*)d_in[12];
    const float* rsn_b2 = (const float*)d_in[13];
    const float* q_w    = (const float*)d_in[14];
    const float* q_b    = (const float*)d_in[15];
    const float* k_w    = (const float*)d_in[16];
    const float* k_b    = (const float*)d_in[17];
    const float* v_w    = (const float*)d_in[18];
    const float* v_b    = (const float*)d_in[19];
    const float* o_w    = (const float*)d_in[20];
    const float* o_b    = (const float*)d_in[21];
    const float* tmp_w1 = (const float*)d_in[22];
    const float* tmp_b1 = (const float*)d_in[23];
    const float* tmp_g  = (const float*)d_in[24];
    const float* tmp_be = (const float*)d_in[25];
    const float* tmp_w2 = (const float*)d_in[26];
    const float* tmp_b2 = (const float*)d_in[27];
    const float* norm_g = (const float*)d_in[28];
    const float* norm_b = (const float*)d_in[29];
    float* out = (float*)d_out;

    float *Himp, *xi, *Hrsn, *reasoned, *Q, *K, *V, *attn, *proj, *part, *rmean, *temp;
    cudaGetSymbolAddress((void**)&Himp,     g_Himp);
    cudaGetSymbolAddress((void**)&xi,       g_xi);
    cudaGetSymbolAddress((void**)&Hrsn,     g_Hrsn);
    cudaGetSymbolAddress((void**)&reasoned, g_reasoned);
    cudaGetSymbolAddress((void**)&Q,        g_Q);
    cudaGetSymbolAddress((void**)&K,        g_K);
    cudaGetSymbolAddress((void**)&V,        g_V);
    cudaGetSymbolAddress((void**)&attn,     g_attn);
    cudaGetSymbolAddress((void**)&proj,     g_proj);
    cudaGetSymbolAddress((void**)&part,     g_part);
    cudaGetSymbolAddress((void**)&rmean,    g_rmean);
    cudaGetSymbolAddress((void**)&temp,     g_temp);

    // 1. importance net first linear: [4096,1024]@[1024,512]
    sgemm_bias<<<dim3(CH/GBN, NT/GBM), 256>>>(x, imp_w1, imp_b1, Himp, NT, CH, Cz);
    // 2. LN + GELU (in place)
    ln_gelu_kernel<CH><<<NT, 256>>>(Himp, imp_g, imp_be);
    // 3. gate: xi = x * importance
    gate_xi_kernel<<<NT, 256>>>(Himp, imp_w2, imp_b2, x, xi);
    // 4. reasoning first linear
    sgemm_bias<<<dim3(Cz/GBN, NT/GBM), 256>>>(xi, rsn_w1, rsn_b1, Hrsn, NT, Cz, Cz);
    // 5. LN + GELU
    ln_gelu_kernel<Cz><<<NT, 256>>>(Hrsn, rsn_g, rsn_be);
    // 6. reasoning second linear
    sgemm_bias<<<dim3(Cz/GBN, NT/GBM), 256>>>(Hrsn, rsn_w2, rsn_b2, reasoned, NT, Cz, Cz);
    // 7. Q/K/V projections
    sgemm_bias<<<dim3(Cz/GBN, NT/GBM), 256>>>(reasoned, q_w, q_b, Q, NT, Cz, Cz);
    sgemm_bias<<<dim3(Cz/GBN, NT/GBM), 256>>>(xi,       k_w, k_b, K, NT, Cz, Cz);
    sgemm_bias<<<dim3(Cz/GBN, NT/GBM), 256>>>(x,        v_w, v_b, V, NT, Cz, Cz);
    // 8. column mean of reasoned over T
    colmean_part<<<dim3(Cz/256, Bz, 8), 256>>>(reasoned, part);
    colmean_fin<<<dim3(Cz/256, Bz), 256>>>(part, rmean);
    // 9. temperature net
    temp_kernel<<<Bz, 512>>>(rmean, tmp_w1, tmp_b1, tmp_g, tmp_be, tmp_w2, tmp_b2, temp);
    // 10. attention
    flash_attn_kernel<<<dim3(Tz/FBQ, Hh, Bz), FBQ>>>(Q, K, V, amask, temp, attn);
    // 11. output projection
    sgemm_bias<<<dim3(Cz/GBN, NT/GBM), 256>>>(attn, o_w, o_b, proj, NT, Cz, Cz);
    // 12. residual + LN -> out
    resid_ln_kernel<<<NT, 256>>>(x, proj, norm_g, norm_b, out);
}

// round 6
// speedup vs baseline: 1.1863x; 1.1863x over previous
#include <cuda_runtime.h>
#include <cuda_bf16.h>
#include <math.h>
#include <cstdint>
#include <mma.h>

using namespace nvcuda;

// Problem constants
#define Bz 2
#define Tz 2048
#define Cz 1024
#define Hh 16
#define Dd 64
#define CH 512
#define NT (Bz*Tz)          // 4096 rows

// ---------------- scratch (device globals; no runtime alloc) ----------------
__device__ float g_Himp[NT*CH];
__device__ float g_xi[NT*Cz];
__device__ float g_Hrsn[NT*Cz];
__device__ float g_reasoned[NT*Cz];
__device__ float g_Q[NT*Cz];
__device__ float g_K[NT*Cz];
__device__ float g_V[NT*Cz];
__device__ float g_attn[NT*Cz];
__device__ float g_proj[NT*Cz];
__device__ float g_part[16*Cz];
__device__ float g_rmean[Bz*Cz];
__device__ float g_temp[Bz*Hh];
__device__ float g_xr[NT*Cz];          // x rounded to tf32
// transposed (N-major -> [N,K] K-contiguous) + tf32-rounded weights
__device__ float g_WtImp[CH*Cz];
__device__ float g_WtRsn1[Cz*Cz];
__device__ float g_WtRsn2[Cz*Cz];
__device__ float g_WtQ[Cz*Cz];
__device__ float g_WtK[Cz*Cz];
__device__ float g_WtV[Cz*Cz];
__device__ float g_WtO[Cz*Cz];

// ---------------- helpers ----------------
__device__ __forceinline__ uint32_t smem_to_u32(const void* p) {
    uint32_t a;
    asm("{ .reg .u64 t; cvta.to.shared.u64 t, %1; cvt.u32.u64 %0, t; }" : "=r"(a) : "l"(p));
    return a;
}
__device__ __forceinline__ float to_tf32(float f) {
    uint32_t u; asm("cvt.rna.tf32.f32 %0, %1;" : "=r"(u) : "f"(f));
    return __uint_as_float(u);
}
__device__ __forceinline__ void cp_async16(uint32_t dst, const void* src) {
    asm volatile("cp.async.cg.shared.global [%0], [%1], 16;" :: "r"(dst), "l"(src) : "memory");
}
__device__ __forceinline__ void cp_commit() { asm volatile("cp.async.commit_group;" ::: "memory"); }
template<int N> __device__ __forceinline__ void cp_wait() {
    asm volatile("cp.async.wait_group %0;" :: "n"(N) : "memory");
}

__device__ __forceinline__ float blockReduceSum(float v) {
    __shared__ float sh[32];
    int lane = threadIdx.x & 31, wid = threadIdx.x >> 5;
    #pragma unroll
    for (int o = 16; o; o >>= 1) v += __shfl_down_sync(0xffffffffu, v, o);
    if (lane == 0) sh[wid] = v;
    __syncthreads();
    int nw = blockDim.x >> 5;
    v = (threadIdx.x < nw) ? sh[threadIdx.x] : 0.f;
    if (wid == 0) {
        #pragma unroll
        for (int o = 16; o; o >>= 1) v += __shfl_down_sync(0xffffffffu, v, o);
        if (lane == 0) sh[0] = v;
    }
    __syncthreads();
    float r = sh[0];
    __syncthreads();
    return r;
}

__device__ __forceinline__ float gelu_exact(float x) {
    return 0.5f * x * (1.0f + erff(x * 0.70710678118654752f));
}

// ---------------- wmma tf32 GEMM: C[4096,N] = A[4096,1024] @ Wt[N,1024]^T + bias ----------------
// CTA tile 128x128, BK=32, 8 warps (2x4), warp tile 64x32 (4x2 frags of 16x16).
// A row-major in smem (ld 36), B = Wt rows are K-contiguous -> col_major frag (ld 36).
// cp.async double buffer; smem epilogue for coalesced bias-add store.
#define GLD  36                    // padded leading dim (floats), %4==0
#define GSTG (128*GLD)             // 4608 floats per A or B tile
#define GSTAGE_FLOATS (2*GSTG)     // A+B per stage = 9216 floats
#define GSMEM_BYTES (2*GSTAGE_FLOATS*4)   // 73728 bytes (>= epilogue 128*132*4=67584)
#define ELD 132

__global__ __launch_bounds__(256) void gemm_tf32(
    const float* __restrict__ A, const float* __restrict__ Wt,
    const float* __restrict__ bias, float* __restrict__ C,
    int N, int round_out)
{
    extern __shared__ float smf[];
    uint32_t sb = smem_to_u32(smf);
    const int tid = threadIdx.x;
    const int wid = tid >> 5;
    const int wm = wid >> 2;          // 0..1
    const int wn = wid & 3;           // 0..3
    const int bx = blockIdx.x;        // N tile
    const int by = blockIdx.y;        // M tile

    wmma::fragment<wmma::accumulator, 16, 16, 8, float> acc[4][2];
    #pragma unroll
    for (int mi = 0; mi < 4; mi++)
        #pragma unroll
        for (int ni = 0; ni < 2; ni++)
            wmma::fill_fragment(acc[mi][ni], 0.0f);

    const float* Abase = A  + (size_t)by * 128 * Cz;
    const float* Bbase = Wt + (size_t)bx * 128 * Cz;

    auto load_stage = [&](int s, int kc) {
        uint32_t ab = sb + (uint32_t)s * GSTAGE_FLOATS * 4;
        uint32_t bb = ab + GSTG * 4;
        #pragma unroll
        for (int i = 0; i < 4; i++) {
            int idx = i * 256 + tid;
            int r = idx >> 3, c = (idx & 7) * 4;
            uint32_t soff = (uint32_t)(r * GLD + c) * 4;
            cp_async16(ab + soff, Abase + (size_t)r * Cz + kc * 32 + c);
            cp_async16(bb + soff, Bbase + (size_t)r * Cz + kc * 32 + c);
        }
        cp_commit();
    };

    load_stage(0, 0);

    for (int kc = 0; kc < 32; kc++) {
        int s = kc & 1;
        if (kc + 1 < 32) { load_stage(s ^ 1, kc + 1); cp_wait<1>(); }
        else             { cp_wait<0>(); }
        __syncthreads();

        const float* As = smf + s * GSTAGE_FLOATS;
        const float* Bs = As + GSTG;

        #pragma unroll
        for (int kk = 0; kk < 4; kk++) {
            wmma::fragment<wmma::matrix_a, 16, 16, 8, wmma::precision::tf32, wmma::row_major> af[4];
            wmma::fragment<wmma::matrix_b, 16, 16, 8, wmma::precision::tf32, wmma::col_major> bf[2];
            #pragma unroll
            for (int mi = 0; mi < 4; mi++) {
                wmma::load_matrix_sync(af[mi], As + (wm * 64 + mi * 16) * GLD + kk * 8, GLD);
                #pragma unroll
                for (int e = 0; e < af[mi].num_elements; e++)
                    af[mi].x[e] = wmma::__float_to_tf32(af[mi].x[e]);
            }
            #pragma unroll
            for (int ni = 0; ni < 2; ni++) {
                wmma::load_matrix_sync(bf[ni], Bs + (wn * 32 + ni * 16) * GLD + kk * 8, GLD);
                #pragma unroll
                for (int e = 0; e < bf[ni].num_elements; e++)
                    bf[ni].x[e] = wmma::__float_to_tf32(bf[ni].x[e]);
            }
            #pragma unroll
            for (int mi = 0; mi < 4; mi++)
                #pragma unroll
                for (int ni = 0; ni < 2; ni++)
                    wmma::mma_sync(acc[mi][ni], af[mi], bf[ni], acc[mi][ni]);
        }
        __syncthreads();
    }

    // epilogue: stage accumulators in smem, then coalesced bias-add stores
    #pragma unroll
    for (int mi = 0; mi < 4; mi++)
        #pragma unroll
        for (int ni = 0; ni < 2; ni++)
            wmma::store_matrix_sync(smf + (wm * 64 + mi * 16) * ELD + wn * 32 + ni * 16,
                                    acc[mi][ni], ELD, wmma::mem_row_major);
    __syncthreads();

    #pragma unroll
    for (int i = 0; i < 16; i++) {
        int idx = i * 256 + tid;
        int r = idx >> 5, c = (idx & 31) * 4;
        const float* bp = bias + bx * 128 + c;
        float4 o;
        o.x = smf[r * ELD + c + 0] + bp[0];
        o.y = smf[r * ELD + c + 1] + bp[1];
        o.z = smf[r * ELD + c + 2] + bp[2];
        o.w = smf[r * ELD + c + 3] + bp[3];
        if (round_out) {
            o.x = to_tf32(o.x); o.y = to_tf32(o.y);
            o.z = to_tf32(o.z); o.w = to_tf32(o.w);
        }
        *(float4*)&C[(size_t)(by * 128 + r) * N + bx * 128 + c] = o;
    }
}

// ---------------- transpose + round weights: Wt[n*K+k] = rna_tf32(W[k*N+n]) ----------------
__global__ void transpose_round(const float* __restrict__ W, float* __restrict__ Wt,
                                int K, int N)
{
    __shared__ float t[32][33];
    int nb = blockIdx.x * 32, kb = blockIdx.y * 32;
    #pragma unroll
    for (int i = threadIdx.y; i < 32; i += 8)
        t[i][threadIdx.x] = W[(size_t)(kb + i) * N + nb + threadIdx.x];
    __syncthreads();
    #pragma unroll
    for (int i = threadIdx.y; i < 32; i += 8)
        Wt[(size_t)(nb + i) * K + kb + threadIdx.x] = to_tf32(t[threadIdx.x][i]);
}

__global__ void round_tf32_kernel(const float* __restrict__ in, float* __restrict__ out) {
    int i = blockIdx.x * 256 + threadIdx.x;
    out[i] = to_tf32(in[i]);
}

// ---------------- in-place LayerNorm + GELU over rows (output rounded to tf32) ----------------
template<int COLS>
__global__ __launch_bounds__(256) void ln_gelu_kernel(
    float* __restrict__ X, const float* __restrict__ g, const float* __restrict__ beta)
{
    const int row = blockIdx.x;
    float* xr = X + (size_t)row * COLS;
    constexpr int PT = COLS / 256;
    float v[PT];
    float s = 0.f;
    #pragma unroll
    for (int i = 0; i < PT; i++) { v[i] = xr[threadIdx.x + i * 256]; s += v[i]; }
    float mean = blockReduceSum(s) * (1.0f / COLS);
    float s2 = 0.f;
    #pragma unroll
    for (int i = 0; i < PT; i++) { float d = v[i] - mean; s2 += d * d; }
    float var = blockReduceSum(s2) * (1.0f / COLS);
    float rstd = rsqrtf(var + 1e-5f);
    #pragma unroll
    for (int i = 0; i < PT; i++) {
        int c = threadIdx.x + i * 256;
        float y = (v[i] - mean) * rstd * g[c] + beta[c];
        xr[c] = to_tf32(gelu_exact(y));
    }
}

// ---------------- importance gate: imp = max(sigmoid(H@w2+b2),1e-6); xi = round(x*imp) ----------------
__global__ __launch_bounds__(256) void gate_xi_kernel(
    const float* __restrict__ H, const float* __restrict__ w2, const float* __restrict__ b2,
    const float* __restrict__ x, float* __restrict__ xi)
{
    const int row = blockIdx.x;
    float p = 0.f;
    const float* hr = H + (size_t)row * CH;
    for (int c = threadIdx.x; c < CH; c += 256) p += hr[c] * w2[c];
    float sum = blockReduceSum(p);
    float sg = 1.0f / (1.0f + expf(-(sum + b2[0])));
    float imp = fmaxf(sg, 1e-6f);
    const float* xr = x + (size_t)row * Cz;
    float* xo = xi + (size_t)row * Cz;
    for (int c = threadIdx.x; c < Cz; c += 256) xo[c] = to_tf32(xr[c] * imp);
}

// ---------------- column mean over T (two stage, deterministic) ----------------
__global__ void colmean_part(const float* __restrict__ R, float* __restrict__ part) {
    int c = blockIdx.x * 256 + threadIdx.x;
    int b = blockIdx.y;
    int ch = blockIdx.z;
    float s = 0.f;
    int t0 = ch * 256;
    for (int t = t0; t < t0 + 256; t++)
        s += R[((size_t)(b * Tz + t)) * Cz + c];
    part[(ch * Bz + b) * Cz + c] = s;
}
__global__ void colmean_fin(const float* __restrict__ part, float* __restrict__ out) {
    int c = blockIdx.x * 256 + threadIdx.x;
    int b = blockIdx.y;
    float s = 0.f;
    for (int ch = 0; ch < 8; ch++) s += part[(ch * Bz + b) * Cz + c];
    out[b * Cz + c] = s * (1.0f / Tz);
}

// ---------------- temperature net: [B,C] -> [B,H] ----------------
__global__ __launch_bounds__(512) void temp_kernel(
    const float* __restrict__ rmean,
    const float* __restrict__ w1, const float* __restrict__ b1,
    const float* __restrict__ g, const float* __restrict__ beta,
    const float* __restrict__ w2, const float* __restrict__ b2,
    float* __restrict__ temp)
{
    const int b = blockIdx.x;
    const int tid = threadIdx.x;
    __shared__ float hsm[CH];
    const float* xr = rmean + b * Cz;
    float acc = b1[tid];
    for (int k = 0; k < Cz; k++) acc = fmaf(xr[k], w1[k * CH + tid], acc);
    float mean = blockReduceSum(acc) * (1.0f / CH);
    float d = acc - mean;
    float var = blockReduceSum(d * d) * (1.0f / CH);
    float rstd = rsqrtf(var + 1e-5f);
    float y = d * rstd * g[tid] + beta[tid];
    hsm[tid] = gelu_exact(y);
    __syncthreads();
    if (tid < Hh) {
        float a2 = b2[tid];
        for (int k = 0; k < CH; k++) a2 = fmaf(hsm[k], w2[k * Hh + tid], a2);
        float sp = (a2 > 20.f) ? a2 : log1pf(expf(a2));
        temp[b * Hh + tid] = sp + 0.5f;
    }
}

// ---------------- flash attention (output rounded to tf32 for o-proj) ----------------
#define FBQ 128
#define FBK 64
__global__ __launch_bounds__(128) void flash_attn_kernel(
    const float* __restrict__ Q, const float* __restrict__ Kp,
    const float* __restrict__ Vp, const int* __restrict__ mask,
    const float* __restrict__ temp, float* __restrict__ O)
{
    __shared__ float Ks[FBK][Dd];
    __shared__ float Vs[FBK][Dd];
    __shared__ unsigned char Ms[FBQ][FBK];

    const int b = blockIdx.z, h = blockIdx.y, qt = blockIdx.x;
    const int tid = threadIdx.x;
    const int qi = qt * FBQ + tid;
    const float sc = 0.125f * temp[b * Hh + h];

    float q[Dd];
    const float* qrow = Q + ((size_t)(b * Tz + qi)) * Cz + h * Dd;
    #pragma unroll
    for (int dd = 0; dd < Dd; dd += 4) {
        float4 t = *(const float4*)(qrow + dd);
        q[dd] = t.x; q[dd+1] = t.y; q[dd+2] = t.z; q[dd+3] = t.w;
    }

    float m = -1e30f, l = 0.f;
    float acc[Dd];
    #pragma unroll
    for (int dd = 0; dd < Dd; dd++) acc[dd] = 0.f;

    const int* mbase = mask + ((size_t)b * Tz + (size_t)qt * FBQ) * Tz;

    for (int k0 = 0; k0 < Tz; k0 += FBK) {
        #pragma unroll
        for (int i = tid; i < FBK * (Dd / 4); i += FBQ) {
            int r = i >> 4, c4 = (i & 15) * 4;
            size_t goff = ((size_t)(b * Tz + k0 + r)) * Cz + h * Dd + c4;
            *(float4*)&Ks[r][c4] = *(const float4*)(Kp + goff);
            *(float4*)&Vs[r][c4] = *(const float4*)(Vp + goff);
        }
        #pragma unroll
        for (int i = tid; i < FBQ * (FBK / 4); i += FBQ) {
            int r = i >> 4, c4 = (i & 15) * 4;
            int4 mv = *(const int4*)(mbase + (size_t)r * Tz + k0 + c4);
            Ms[r][c4 + 0] = mv.x ? 1 : 0;
            Ms[r][c4 + 1] = mv.y ? 1 : 0;
            Ms[r][c4 + 2] = mv.z ? 1 : 0;
            Ms[r][c4 + 3] = mv.w ? 1 : 0;
        }
        __syncthreads();

        #pragma unroll 1
        for (int j0 = 0; j0 < FBK; j0 += 16) {
            float s[16];
            #pragma unroll
            for (int j = 0; j < 16; j++) {
                float a = 0.f;
                #pragma unroll
                for (int dd = 0; dd < Dd; dd += 4) {
                    float4 kv = *(const float4*)&Ks[j0 + j][dd];
                    a = fmaf(q[dd], kv.x, a);
                    a = fmaf(q[dd+1], kv.y, a);
                    a = fmaf(q[dd+2], kv.z, a);
                    a = fmaf(q[dd+3], kv.w, a);
                }
                s[j] = Ms[tid][j0 + j] ? a * sc : -1e30f;
            }
            float cm = s[0];
            #pragma unroll
            for (int j = 1; j < 16; j++) cm = fmaxf(cm, s[j]);
            float mnew = fmaxf(m, cm);
            float corr = __expf(m - mnew);
            l *= corr;
            #pragma unroll
            for (int dd = 0; dd < Dd; dd++) acc[dd] *= corr;
            #pragma unroll
            for (int j = 0; j < 16; j++) {
                float p = __expf(s[j] - mnew);
                l += p;
                #pragma unroll
                for (int dd = 0; dd < Dd; dd += 4) {
                    float4 vv = *(const float4*)&Vs[j0 + j][dd];
                    acc[dd]   = fmaf(p, vv.x, acc[dd]);
                    acc[dd+1] = fmaf(p, vv.y, acc[dd+1]);
                    acc[dd+2] = fmaf(p, vv.z, acc[dd+2]);
                    acc[dd+3] = fmaf(p, vv.w, acc[dd+3]);
                }
            }
            m = mnew;
        }
        __syncthreads();
    }

    float inv = 1.0f / l;
    float* orow = O + ((size_t)(b * Tz + qi)) * Cz + h * Dd;
    #pragma unroll
    for (int dd = 0; dd < Dd; dd += 4) {
        float4 o;
        o.x = to_tf32(acc[dd] * inv);   o.y = to_tf32(acc[dd+1] * inv);
        o.z = to_tf32(acc[dd+2] * inv); o.w = to_tf32(acc[dd+3] * inv);
        *(float4*)(orow + dd) = o;
    }
}

// ---------------- residual + LayerNorm epilogue ----------------
__global__ __launch_bounds__(256) void resid_ln_kernel(
    const float* __restrict__ x, const float* __restrict__ p,
    const float* __restrict__ g, const float* __restrict__ beta,
    float* __restrict__ out)
{
    const int row = blockIdx.x;
    const float* xr = x + (size_t)row * Cz;
    const float* pr = p + (size_t)row * Cz;
    float v[4];
    float s = 0.f;
    #pragma unroll
    for (int i = 0; i < 4; i++) {
        int c = threadIdx.x + i * 256;
        v[i] = xr[c] + pr[c];
        s += v[i];
    }
    float mean = blockReduceSum(s) * (1.0f / Cz);
    float s2 = 0.f;
    #pragma unroll
    for (int i = 0; i < 4; i++) { float d = v[i] - mean; s2 += d * d; }
    float var = blockReduceSum(s2) * (1.0f / Cz);
    float rstd = rsqrtf(var + 1e-5f);
    #pragma unroll
    for (int i = 0; i < 4; i++) {
        int c = threadIdx.x + i * 256;
        out[(size_t)row * Cz + c] = (v[i] - mean) * rstd * g[c] + beta[c];
    }
}

// ---------------- launch ----------------
extern "C" void kernel_launch(void* const* d_in, const int* in_sizes, int n_in,
                              void* d_out, int out_size)
{
    const float* x      = (const float*)d_in[0];
    const int*   amask  = (const int*)  d_in[1];
    const float* imp_w1 = (const float*)d_in[2];
    const float* imp_b1 = (const float*)d_in[3];
    const float* imp_g  = (const float*)d_in[4];
    const float* imp_be = (const float*)d_in[5];
    const float* imp_w2 = (const float*)d_in[6];
    const float* imp_b2 = (const float*)d_in[7];
    const float* rsn_w1 = (const float*)d_in[8];
    const float* rsn_b1 = (const float*)d_in[9];
    const float* rsn_g  = (const float*)d_in[10];
    const float* rsn_be = (const float*)d_in[11];
    const float* rsn_w2 = (const float*)d_in[12];
    const float* rsn_b2 = (const float*)d_in[13];
    const float* q_w    = (const float*)d_in[14];
    const float* q_b    = (const float*)d_in[15];
    const float* k_w    = (const float*)d_in[16];
    const float* k_b    = (const float*)d_in[17];
    const float* v_w    = (const float*)d_in[18];
    const float* v_b    = (const float*)d_in[19];
    const float* o_w    = (const float*)d_in[20];
    const float* o_b    = (const float*)d_in[21];
    const float* tmp_w1 = (const float*)d_in[22];
    const float* tmp_b1 = (const float*)d_in[23];
    const float* tmp_g  = (const float*)d_in[24];
    const float* tmp_be = (const float*)d_in[25];
    const float* tmp_w2 = (const float*)d_in[26];
    const float* tmp_b2 = (const float*)d_in[27];
    const float* norm_g = (const float*)d_in[28];
    const float* norm_b = (const float*)d_in[29];
    float* out = (float*)d_out;

    float *Himp, *xi, *Hrsn, *reasoned, *Q, *K, *V, *attn, *proj, *part, *rmean, *temp, *xr;
    float *WtImp, *WtRsn1, *WtRsn2, *WtQ, *WtK, *WtV, *WtO;
    cudaGetSymbolAddress((void**)&Himp,     g_Himp);
    cudaGetSymbolAddress((void**)&xi,       g_xi);
    cudaGetSymbolAddress((void**)&Hrsn,     g_Hrsn);
    cudaGetSymbolAddress((void**)&reasoned, g_reasoned);
    cudaGetSymbolAddress((void**)&Q,        g_Q);
    cudaGetSymbolAddress((void**)&K,        g_K);
    cudaGetSymbolAddress((void**)&V,        g_V);
    cudaGetSymbolAddress((void**)&attn,     g_attn);
    cudaGetSymbolAddress((void**)&proj,     g_proj);
    cudaGetSymbolAddress((void**)&part,     g_part);
    cudaGetSymbolAddress((void**)&rmean,    g_rmean);
    cudaGetSymbolAddress((void**)&temp,     g_temp);
    cudaGetSymbolAddress((void**)&xr,       g_xr);
    cudaGetSymbolAddress((void**)&WtImp,    g_WtImp);
    cudaGetSymbolAddress((void**)&WtRsn1,   g_WtRsn1);
    cudaGetSymbolAddress((void**)&WtRsn2,   g_WtRsn2);
    cudaGetSymbolAddress((void**)&WtQ,      g_WtQ);
    cudaGetSymbolAddress((void**)&WtK,      g_WtK);
    cudaGetSymbolAddress((void**)&WtV,      g_WtV);
    cudaGetSymbolAddress((void**)&WtO,      g_WtO);

    cudaFuncSetAttribute(gemm_tf32, cudaFuncAttributeMaxDynamicSharedMemorySize, GSMEM_BYTES);

    dim3 tb(32, 8);
    // weight transposes + tf32 rounding
    transpose_round<<<dim3(CH/32, Cz/32), tb>>>(imp_w1, WtImp, Cz, CH);
    transpose_round<<<dim3(Cz/32, Cz/32), tb>>>(rsn_w1, WtRsn1, Cz, Cz);
    transpose_round<<<dim3(Cz/32, Cz/32), tb>>>(rsn_w2, WtRsn2, Cz, Cz);
    transpose_round<<<dim3(Cz/32, Cz/32), tb>>>(q_w, WtQ, Cz, Cz);
    transpose_round<<<dim3(Cz/32, Cz/32), tb>>>(k_w, WtK, Cz, Cz);
    transpose_round<<<dim3(Cz/32, Cz/32), tb>>>(v_w, WtV, Cz, Cz);
    transpose_round<<<dim3(Cz/32, Cz/32), tb>>>(o_w, WtO, Cz, Cz);
    round_tf32_kernel<<<NT*Cz/256, 256>>>(x, xr);

    // 1. importance net first linear
    gemm_tf32<<<dim3(CH/128, NT/128), 256, GSMEM_BYTES>>>(xr, WtImp, imp_b1, Himp, CH, 0);
    // 2. LN + GELU (in place, rounds)
    ln_gelu_kernel<CH><<<NT, 256>>>(Himp, imp_g, imp_be);
    // 3. gate: xi = round(x * importance)
    gate_xi_kernel<<<NT, 256>>>(Himp, imp_w2, imp_b2, x, xi);
    // 4. reasoning first linear
    gemm_tf32<<<dim3(Cz/128, NT/128), 256, GSMEM_BYTES>>>(xi, WtRsn1, rsn_b1, Hrsn, Cz, 0);
    // 5. LN + GELU (rounds)
    ln_gelu_kernel<Cz><<<NT, 256>>>(Hrsn, rsn_g, rsn_be);
    // 6. reasoning second linear (round output: feeds q-proj GEMM)
    gemm_tf32<<<dim3(Cz/128, NT/128), 256, GSMEM_BYTES>>>(Hrsn, WtRsn2, rsn_b2, reasoned, Cz, 1);
    // 7. Q/K/V projections
    gemm_tf32<<<dim3(Cz/128, NT/128), 256, GSMEM_BYTES>>>(reasoned, WtQ, q_b, Q, Cz, 0);
    gemm_tf32<<<dim3(Cz/128, NT/128), 256, GSMEM_BYTES>>>(xi,       WtK, k_b, K, Cz, 0);
    gemm_tf32<<<dim3(Cz/128, NT/128), 256, GSMEM_BYTES>>>(xr,       WtV, v_b, V, Cz, 0);
    // 8. column mean of reasoned over T
    colmean_part<<<dim3(Cz/256, Bz, 8), 256>>>(reasoned, part);
    colmean_fin<<<dim3(Cz/256, Bz), 256>>>(part, rmean);
    // 9. temperature net
    temp_kernel<<<Bz, 512>>>(rmean, tmp_w1, tmp_b1, tmp_g, tmp_be, tmp_w2, tmp_b2, temp);
    // 10. attention (rounds output)
    flash_attn_kernel<<<dim3(Tz/FBQ, Hh, Bz), FBQ>>>(Q, K, V, amask, temp, attn);
    // 11. output projection
    gemm_tf32<<<dim3(Cz/128, NT/128), 256, GSMEM_BYTES>>>(attn, WtO, o_b, proj, Cz, 0);
    // 12. residual + LN -> out
    resid_ln_kernel<<<NT, 256>>>(x, proj, norm_g, norm_b, out);
}

// round 8
// speedup vs baseline: 1.6461x; 1.3876x over previous
#include <cuda_runtime.h>
#include <cuda_bf16.h>
#include <math.h>
#include <cstdint>
#include <mma.h>

using namespace nvcuda;

// Problem constants
#define Bz 2
#define Tz 2048
#define Cz 1024
#define Hh 16
#define Dd 64
#define CH 512
#define NT (Bz*Tz)          // 4096 rows

// ---------------- scratch (device globals; no runtime alloc) ----------------
__device__ float g_Himp[NT*CH];
__device__ float g_xi[NT*Cz];
__device__ float g_Hrsn[NT*Cz];
__device__ float g_reasoned[NT*Cz];
__device__ float g_Q[NT*Cz];
__device__ float g_K[NT*Cz];
__device__ float g_V[NT*Cz];
__device__ float g_attn[NT*Cz];
__device__ float g_proj[NT*Cz];
__device__ float g_part[16*Cz];
__device__ float g_rmean[Bz*Cz];
__device__ float g_temp[Bz*Hh];
__device__ float g_xr[NT*Cz];          // x rounded to tf32
__device__ uint32_t g_mbits[(size_t)Bz*Tz*Tz/32];   // packed attention mask (1MB)
// transposed (N-major -> [N,K] K-contiguous) + tf32-rounded weights
__device__ float g_WtImp[CH*Cz];
__device__ float g_WtRsn1[Cz*Cz];
__device__ float g_WtRsn2[Cz*Cz];
__device__ float g_WtQ[Cz*Cz];
__device__ float g_WtK[Cz*Cz];
__device__ float g_WtV[Cz*Cz];
__device__ float g_WtO[Cz*Cz];

// ---------------- helpers ----------------
__device__ __forceinline__ uint32_t smem_to_u32(const void* p) {
    uint32_t a;
    asm("{ .reg .u64 t; cvta.to.shared.u64 t, %1; cvt.u32.u64 %0, t; }" : "=r"(a) : "l"(p));
    return a;
}
__device__ __forceinline__ float to_tf32(float f) {
    uint32_t u; asm("cvt.rna.tf32.f32 %0, %1;" : "=r"(u) : "f"(f));
    return __uint_as_float(u);
}
__device__ __forceinline__ void cp_async16(uint32_t dst, const void* src) {
    asm volatile("cp.async.cg.shared.global [%0], [%1], 16;" :: "r"(dst), "l"(src) : "memory");
}
__device__ __forceinline__ void cp_commit() { asm volatile("cp.async.commit_group;" ::: "memory"); }
template<int N> __device__ __forceinline__ void cp_wait() {
    asm volatile("cp.async.wait_group %0;" :: "n"(N) : "memory");
}

__device__ __forceinline__ float blockReduceSum(float v) {
    __shared__ float sh[32];
    int lane = threadIdx.x & 31, wid = threadIdx.x >> 5;
    #pragma unroll
    for (int o = 16; o; o >>= 1) v += __shfl_down_sync(0xffffffffu, v, o);
    if (lane == 0) sh[wid] = v;
    __syncthreads();
    int nw = blockDim.x >> 5;
    v = (threadIdx.x < nw) ? sh[threadIdx.x] : 0.f;
    if (wid == 0) {
        #pragma unroll
        for (int o = 16; o; o >>= 1) v += __shfl_down_sync(0xffffffffu, v, o);
        if (lane == 0) sh[0] = v;
    }
    __syncthreads();
    float r = sh[0];
    __syncthreads();
    return r;
}

__device__ __forceinline__ float gelu_exact(float x) {
    return 0.5f * x * (1.0f + erff(x * 0.70710678118654752f));
}

// ---------------- wmma tf32 GEMM: C[4096,N] = A[4096,1024] @ Wt[N,1024]^T + bias ----------------
#define GLD  36
#define GSTG (128*GLD)
#define GSTAGE_FLOATS (2*GSTG)
#define GSMEM_BYTES (2*GSTAGE_FLOATS*4)
#define ELD 132

__global__ __launch_bounds__(256) void gemm_tf32(
    const float* __restrict__ A, const float* __restrict__ Wt,
    const float* __restrict__ bias, float* __restrict__ C,
    int N, int round_out)
{
    extern __shared__ float smf[];
    uint32_t sb = smem_to_u32(smf);
    const int tid = threadIdx.x;
    const int wid = tid >> 5;
    const int wm = wid >> 2;
    const int wn = wid & 3;
    const int bx = blockIdx.x;
    const int by = blockIdx.y;

    wmma::fragment<wmma::accumulator, 16, 16, 8, float> acc[4][2];
    #pragma unroll
    for (int mi = 0; mi < 4; mi++)
        #pragma unroll
        for (int ni = 0; ni < 2; ni++)
            wmma::fill_fragment(acc[mi][ni], 0.0f);

    const float* Abase = A  + (size_t)by * 128 * Cz;
    const float* Bbase = Wt + (size_t)bx * 128 * Cz;

    auto load_stage = [&](int s, int kc) {
        uint32_t ab = sb + (uint32_t)s * GSTAGE_FLOATS * 4;
        uint32_t bb = ab + GSTG * 4;
        #pragma unroll
        for (int i = 0; i < 4; i++) {
            int idx = i * 256 + tid;
            int r = idx >> 3, c = (idx & 7) * 4;
            uint32_t soff = (uint32_t)(r * GLD + c) * 4;
            cp_async16(ab + soff, Abase + (size_t)r * Cz + kc * 32 + c);
            cp_async16(bb + soff, Bbase + (size_t)r * Cz + kc * 32 + c);
        }
        cp_commit();
    };

    load_stage(0, 0);

    for (int kc = 0; kc < 32; kc++) {
        int s = kc & 1;
        if (kc + 1 < 32) { load_stage(s ^ 1, kc + 1); cp_wait<1>(); }
        else             { cp_wait<0>(); }
        __syncthreads();

        const float* As = smf + s * GSTAGE_FLOATS;
        const float* Bs = As + GSTG;

        #pragma unroll
        for (int kk = 0; kk < 4; kk++) {
            wmma::fragment<wmma::matrix_a, 16, 16, 8, wmma::precision::tf32, wmma::row_major> af[4];
            wmma::fragment<wmma::matrix_b, 16, 16, 8, wmma::precision::tf32, wmma::col_major> bf[2];
            // operands are pre-rounded to tf32 by producers; HW truncation is identity
            #pragma unroll
            for (int mi = 0; mi < 4; mi++)
                wmma::load_matrix_sync(af[mi], As + (wm * 64 + mi * 16) * GLD + kk * 8, GLD);
            #pragma unroll
            for (int ni = 0; ni < 2; ni++)
                wmma::load_matrix_sync(bf[ni], Bs + (wn * 32 + ni * 16) * GLD + kk * 8, GLD);
            #pragma unroll
            for (int mi = 0; mi < 4; mi++)
                #pragma unroll
                for (int ni = 0; ni < 2; ni++)
                    wmma::mma_sync(acc[mi][ni], af[mi], bf[ni], acc[mi][ni]);
        }
        __syncthreads();
    }

    #pragma unroll
    for (int mi = 0; mi < 4; mi++)
        #pragma unroll
        for (int ni = 0; ni < 2; ni++)
            wmma::store_matrix_sync(smf + (wm * 64 + mi * 16) * ELD + wn * 32 + ni * 16,
                                    acc[mi][ni], ELD, wmma::mem_row_major);
    __syncthreads();

    #pragma unroll
    for (int i = 0; i < 16; i++) {
        int idx = i * 256 + tid;
        int r = idx >> 5, c = (idx & 31) * 4;
        const float* bp = bias + bx * 128 + c;
        float4 o;
        o.x = smf[r * ELD + c + 0] + bp[0];
        o.y = smf[r * ELD + c + 1] + bp[1];
        o.z = smf[r * ELD + c + 2] + bp[2];
        o.w = smf[r * ELD + c + 3] + bp[3];
        if (round_out) {
            o.x = to_tf32(o.x); o.y = to_tf32(o.y);
            o.z = to_tf32(o.z); o.w = to_tf32(o.w);
        }
        *(float4*)&C[(size_t)(by * 128 + r) * N + bx * 128 + c] = o;
    }
}

// ---------------- transpose + round weights ----------------
__global__ void transpose_round(const float* __restrict__ W, float* __restrict__ Wt,
                                int K, int N)
{
    __shared__ float t[32][33];
    int nb = blockIdx.x * 32, kb = blockIdx.y * 32;
    #pragma unroll
    for (int i = threadIdx.y; i < 32; i += 8)
        t[i][threadIdx.x] = W[(size_t)(kb + i) * N + nb + threadIdx.x];
    __syncthreads();
    #pragma unroll
    for (int i = threadIdx.y; i < 32; i += 8)
        Wt[(size_t)(nb + i) * K + kb + threadIdx.x] = to_tf32(t[threadIdx.x][i]);
}

__global__ void round_tf32_kernel(const float* __restrict__ in, float* __restrict__ out) {
    int i = blockIdx.x * 256 + threadIdx.x;
    out[i] = to_tf32(in[i]);
}

// ---------------- pack mask to bits (ballot) ----------------
__global__ void pack_mask_kernel(const int* __restrict__ mask, uint32_t* __restrict__ mbits) {
    size_t p = (size_t)blockIdx.x * 256 + threadIdx.x;
    unsigned bit = (mask[p] != 0) ? 1u : 0u;
    uint32_t w = __ballot_sync(0xffffffffu, bit);
    if ((threadIdx.x & 31) == 0) mbits[p >> 5] = w;
}

// ---------------- LN + GELU ----------------
template<int COLS>
__global__ __launch_bounds__(256) void ln_gelu_kernel(
    float* __restrict__ X, const float* __restrict__ g, const float* __restrict__ beta)
{
    const int row = blockIdx.x;
    float* xr = X + (size_t)row * COLS;
    constexpr int PT = COLS / 256;
    float v[PT];
    float s = 0.f;
    #pragma unroll
    for (int i = 0; i < PT; i++) { v[i] = xr[threadIdx.x + i * 256]; s += v[i]; }
    float mean = blockReduceSum(s) * (1.0f / COLS);
    float s2 = 0.f;
    #pragma unroll
    for (int i = 0; i < PT; i++) { float d = v[i] - mean; s2 += d * d; }
    float var = blockReduceSum(s2) * (1.0f / COLS);
    float rstd = rsqrtf(var + 1e-5f);
    #pragma unroll
    for (int i = 0; i < PT; i++) {
        int c = threadIdx.x + i * 256;
        float y = (v[i] - mean) * rstd * g[c] + beta[c];
        xr[c] = to_tf32(gelu_exact(y));
    }
}

// ---------------- importance gate ----------------
__global__ __launch_bounds__(256) void gate_xi_kernel(
    const float* __restrict__ H, const float* __restrict__ w2, const float* __restrict__ b2,
    const float* __restrict__ x, float* __restrict__ xi)
{
    const int row = blockIdx.x;
    float p = 0.f;
    const float* hr = H + (size_t)row * CH;
    for (int c = threadIdx.x; c < CH; c += 256) p += hr[c] * w2[c];
    float sum = blockReduceSum(p);
    float sg = 1.0f / (1.0f + expf(-(sum + b2[0])));
    float imp = fmaxf(sg, 1e-6f);
    const float* xr = x + (size_t)row * Cz;
    float* xo = xi + (size_t)row * Cz;
    for (int c = threadIdx.x; c < Cz; c += 256) xo[c] = to_tf32(xr[c] * imp);
}

// ---------------- column mean ----------------
__global__ void colmean_part(const float* __restrict__ R, float* __restrict__ part) {
    int c = blockIdx.x * 256 + threadIdx.x;
    int b = blockIdx.y;
    int ch = blockIdx.z;
    float s = 0.f;
    int t0 = ch * 256;
    for (int t = t0; t < t0 + 256; t++)
        s += R[((size_t)(b * Tz + t)) * Cz + c];
    part[(ch * Bz + b) * Cz + c] = s;
}
__global__ void colmean_fin(const float* __restrict__ part, float* __restrict__ out) {
    int c = blockIdx.x * 256 + threadIdx.x;
    int b = blockIdx.y;
    float s = 0.f;
    for (int ch = 0; ch < 8; ch++) s += part[(ch * Bz + b) * Cz + c];
    out[b * Cz + c] = s * (1.0f / Tz);
}

// ---------------- temperature net ----------------
__global__ __launch_bounds__(512) void temp_kernel(
    const float* __restrict__ rmean,
    const float* __restrict__ w1, const float* __restrict__ b1,
    const float* __restrict__ g, const float* __restrict__ beta,
    const float* __restrict__ w2, const float* __restrict__ b2,
    float* __restrict__ temp)
{
    const int b = blockIdx.x;
    const int tid = threadIdx.x;
    __shared__ float hsm[CH];
    const float* xr = rmean + b * Cz;
    float acc = b1[tid];
    for (int k = 0; k < Cz; k++) acc = fmaf(xr[k], w1[k * CH + tid], acc);
    float mean = blockReduceSum(acc) * (1.0f / CH);
    float d = acc - mean;
    float var = blockReduceSum(d * d) * (1.0f / CH);
    float rstd = rsqrtf(var + 1e-5f);
    float y = d * rstd * g[tid] + beta[tid];
    hsm[tid] = gelu_exact(y);
    __syncthreads();
    if (tid < Hh) {
        float a2 = b2[tid];
        for (int k = 0; k < CH; k++) a2 = fmaf(hsm[k], w2[k * Hh + tid], a2);
        float sp = (a2 > 20.f) ? a2 : log1pf(expf(a2));
        temp[b * Hh + tid] = sp + 0.5f;
    }
}

// ---------------- wmma tf32 flash attention ----------------
// CTA = (128 q-rows, one head). 256 threads, 8 warps.
// smem floats: Qs[128][68] | Ks[128][68] | Vs[128][64] | S[128][132] | O[128][68] | m,l,corr[128]
#define AQS 0
#define AKS 8704
#define AVS 17408
#define ASS 25600
#define AOS 42496
#define AMS 51200
#define ALS 51328
#define ACS 51456
#define ASM_FLOATS 51584
#define ASM_BYTES (ASM_FLOATS*4)

__global__ __launch_bounds__(256) void flash_wmma_kernel(
    const float* __restrict__ Q, const float* __restrict__ Kp,
    const float* __restrict__ Vp, const uint32_t* __restrict__ mbits,
    const float* __restrict__ temp, float* __restrict__ O)
{
    extern __shared__ float smf[];
    uint32_t sb = smem_to_u32(smf);
    const int tid = threadIdx.x;
    const int wid = tid >> 5;
    const int wm = wid >> 2;          // 0..1
    const int wn = wid & 3;           // 0..3
    const int qt = blockIdx.x, h = blockIdx.y, b = blockIdx.z;
    const int qrow0 = qt * 128;
    const float sc = 0.125f * temp[b * Hh + h];

    // load Q tile [128,64] -> Qs ld 68 (plain loads; once)
    #pragma unroll
    for (int i = 0; i < 8; i++) {
        int idx = i * 256 + tid;
        int r = idx >> 4, c4 = (idx & 15) * 4;
        float4 qv = *(const float4*)(Q + ((size_t)(b * Tz + qrow0 + r)) * Cz + h * Dd + c4);
        *(float4*)&smf[AQS + r * 68 + c4] = qv;
    }
    if (tid < 128) { smf[AMS + tid] = -1e30f; smf[ALS + tid] = 0.f; }

    auto load_K = [&](int k0) {
        #pragma unroll
        for (int i = 0; i < 8; i++) {
            int idx = i * 256 + tid;
            int r = idx >> 4, c4 = (idx & 15) * 4;
            cp_async16(sb + (AKS + r * 68 + c4) * 4,
                       Kp + ((size_t)(b * Tz + k0 + r)) * Cz + h * Dd + c4);
        }
        cp_commit();
    };
    auto load_V = [&](int k0) {
        #pragma unroll
        for (int i = 0; i < 8; i++) {
            int idx = i * 256 + tid;
            int r = idx >> 4, c4 = (idx & 15) * 4;
            cp_async16(sb + (AVS + r * 64 + c4) * 4,
                       Vp + ((size_t)(b * Tz + k0 + r)) * Cz + h * Dd + c4);
        }
        cp_commit();
    };

    load_K(0);
    load_V(0);
    __syncthreads();   // Qs + m/l init visible

    const int NBLK = Tz / 128;   // 16
    for (int blk = 0; blk < NBLK; blk++) {
        int k0 = blk * 128;
        // ---- wait K ready (allow V of this block pending) ----
        cp_wait<1>();
        __syncthreads();

        // ---- S = Q @ K^T ----
        {
            wmma::fragment<wmma::accumulator, 16, 16, 8, float> acc[4][2];
            #pragma unroll
            for (int mi = 0; mi < 4; mi++)
                #pragma unroll
                for (int ni = 0; ni < 2; ni++)
                    wmma::fill_fragment(acc[mi][ni], 0.0f);
            #pragma unroll
            for (int kk = 0; kk < 8; kk++) {
                wmma::fragment<wmma::matrix_a, 16, 16, 8, wmma::precision::tf32, wmma::row_major> af[4];
                wmma::fragment<wmma::matrix_b, 16, 16, 8, wmma::precision::tf32, wmma::col_major> bf[2];
                #pragma unroll
                for (int mi = 0; mi < 4; mi++)
                    wmma::load_matrix_sync(af[mi], smf + AQS + (wm * 64 + mi * 16) * 68 + kk * 8, 68);
                #pragma unroll
                for (int ni = 0; ni < 2; ni++)
                    wmma::load_matrix_sync(bf[ni], smf + AKS + (wn * 32 + ni * 16) * 68 + kk * 8, 68);
                #pragma unroll
                for (int mi = 0; mi < 4; mi++)
                    #pragma unroll
                    for (int ni = 0; ni < 2; ni++)
                        wmma::mma_sync(acc[mi][ni], af[mi], bf[ni], acc[mi][ni]);
            }
            #pragma unroll
            for (int mi = 0; mi < 4; mi++)
                #pragma unroll
                for (int ni = 0; ni < 2; ni++)
                    wmma::store_matrix_sync(smf + ASS + (wm * 64 + mi * 16) * 132 + wn * 32 + ni * 16,
                                            acc[mi][ni], 132, wmma::mem_row_major);
        }
        __syncthreads();

        // Ks free -> prefetch next K
        if (blk + 1 < NBLK) load_K(k0 + 128);

        // ---- softmax (online) : thread -> row r = tid>>1, cols c0 = (tid&1)*64 ----
        {
            int r = tid >> 1, c0 = (tid & 1) * 64;
            size_t mb_idx = (((size_t)(b * Tz + qrow0 + r)) * Tz + k0 + c0) >> 5;
            uint32_t w0 = mbits[mb_idx], w1 = mbits[mb_idx + 1];
            uint64_t mw = (uint64_t)w0 | ((uint64_t)w1 << 32);
            float* Srow = smf + ASS + r * 132 + c0;
            float vmax = -1e30f;
            #pragma unroll
            for (int j = 0; j < 64; j++) {
                float s = Srow[j];
                s = ((mw >> j) & 1ull) ? s * sc : -1e30f;
                Srow[j] = s;
                vmax = fmaxf(vmax, s);
            }
            vmax = fmaxf(vmax, __shfl_xor_sync(0xffffffffu, vmax, 1));
            float mold = smf[AMS + r];
            float mnew = fmaxf(mold, vmax);
            float corr = __expf(mold - mnew);
            float lsum = 0.f;
            #pragma unroll
            for (int j = 0; j < 64; j++) {
                float p = __expf(Srow[j] - mnew);
                lsum += p;
                Srow[j] = to_tf32(p);
            }
            lsum += __shfl_xor_sync(0xffffffffu, lsum, 1);
            if ((tid & 1) == 0) {
                smf[AMS + r] = mnew;
                smf[ALS + r] = smf[ALS + r] * corr + lsum;
                smf[ACS + r] = corr;
            }
        }

        // ---- wait V ready ----
        if (blk + 1 < NBLK) cp_wait<1>(); else cp_wait<0>();
        __syncthreads();

        // ---- PV = P @ V ----  warp: wm2=wid>>2 (64 rows), wn2=wid&3 (16 cols)
        {
            wmma::fragment<wmma::accumulator, 16, 16, 8, float> acc2[4];
            #pragma unroll
            for (int mi = 0; mi < 4; mi++) wmma::fill_fragment(acc2[mi], 0.0f);
            #pragma unroll
            for (int kk = 0; kk < 16; kk++) {
                wmma::fragment<wmma::matrix_b, 16, 16, 8, wmma::precision::tf32, wmma::row_major> bf;
                wmma::load_matrix_sync(bf, smf + AVS + (kk * 8) * 64 + wn * 16, 64);
                #pragma unroll
                for (int mi = 0; mi < 4; mi++) {
                    wmma::fragment<wmma::matrix_a, 16, 16, 8, wmma::precision::tf32, wmma::row_major> af;
                    wmma::load_matrix_sync(af, smf + ASS + (wm * 64 + mi * 16) * 132 + kk * 8, 132);
                    wmma::mma_sync(acc2[mi], af, bf, acc2[mi]);
                }
            }
            __syncthreads();   // all P reads done before overwriting S with PV
            #pragma unroll
            for (int mi = 0; mi < 4; mi++)
                wmma::store_matrix_sync(smf + ASS + (wm * 64 + mi * 16) * 132 + wn * 16,
                                        acc2[mi], 132, wmma::mem_row_major);
        }

        // Vs free -> prefetch next V
        if (blk + 1 < NBLK) load_V(k0 + 128);
        __syncthreads();   // PV staged + corr visible

        // ---- merge into O ----
        if (blk == 0) {
            #pragma unroll
            for (int i = 0; i < 32; i++) {
                int idx = i * 256 + tid;
                int r = idx >> 6, c = idx & 63;
                smf[AOS + r * 68 + c] = smf[ASS + r * 132 + c];
            }
        } else {
            #pragma unroll
            for (int i = 0; i < 32; i++) {
                int idx = i * 256 + tid;
                int r = idx >> 6, c = idx & 63;
                smf[AOS + r * 68 + c] = smf[AOS + r * 68 + c] * smf[ACS + r] + smf[ASS + r * 132 + c];
            }
        }
        __syncthreads();   // merge done before next block's S store
    }

    // ---- write output (rounded to tf32 for o-proj) ----
    #pragma unroll
    for (int i = 0; i < 32; i++) {
        int idx = i * 256 + tid;
        int r = idx >> 6, c = idx & 63;
        float val = smf[AOS + r * 68 + c] / smf[ALS + r];
        O[((size_t)(b * Tz + qrow0 + r)) * Cz + h * Dd + c] = to_tf32(val);
    }
}

// ---------------- residual + LayerNorm epilogue ----------------
__global__ __launch_bounds__(256) void resid_ln_kernel(
    const float* __restrict__ x, const float* __restrict__ p,
    const float* __restrict__ g, const float* __restrict__ beta,
    float* __restrict__ out)
{
    const int row = blockIdx.x;
    const float* xr = x + (size_t)row * Cz;
    const float* pr = p + (size_t)row * Cz;
    float v[4];
    float s = 0.f;
    #pragma unroll
    for (int i = 0; i < 4; i++) {
        int c = threadIdx.x + i * 256;
        v[i] = xr[c] + pr[c];
        s += v[i];
    }
    float mean = blockReduceSum(s) * (1.0f / Cz);
    float s2 = 0.f;
    #pragma unroll
    for (int i = 0; i < 4; i++) { float d = v[i] - mean; s2 += d * d; }
    float var = blockReduceSum(s2) * (1.0f / Cz);
    float rstd = rsqrtf(var + 1e-5f);
    #pragma unroll
    for (int i = 0; i < 4; i++) {
        int c = threadIdx.x + i * 256;
        out[(size_t)row * Cz + c] = (v[i] - mean) * rstd * g[c] + beta[c];
    }
}

// ---------------- launch ----------------
extern "C" void kernel_launch(void* const* d_in, const int* in_sizes, int n_in,
                              void* d_out, int out_size)
{
    const float* x      = (const float*)d_in[0];
    const int*   amask  = (const int*)  d_in[1];
    const float* imp_w1 = (const float*)d_in[2];
    const float* imp_b1 = (const float*)d_in[3];
    const float* imp_g  = (const float*)d_in[4];
    const float* imp_be = (const float*)d_in[5];
    const float* imp_w2 = (const float*)d_in[6];
    const float* imp_b2 = (const float*)d_in[7];
    const float* rsn_w1 = (const float*)d_in[8];
    const float* rsn_b1 = (const float*)d_in[9];
    const float* rsn_g  = (const float*)d_in[10];
    const float* rsn_be = (const float*)d_in[11];
    const float* rsn_w2 = (const float*)d_in[12];
    const float* rsn_b2 = (const float*)d_in[13];
    const float* q_w    = (const float*)d_in[14];
    const float* q_b    = (const float*)d_in[15];
    const float* k_w    = (const float*)d_in[16];
    const float* k_b    = (const float*)d_in[17];
    const float* v_w    = (const float*)d_in[18];
    const float* v_b    = (const float*)d_in[19];
    const float* o_w    = (const float*)d_in[20];
    const float* o_b    = (const float*)d_in[21];
    const float* tmp_w1 = (const float*)d_in[22];
    const float* tmp_b1 = (const float*)d_in[23];
    const float* tmp_g  = (const float*)d_in[24];
    const float* tmp_be = (const float*)d_in[25];
    const float* tmp_w2 = (const float*)d_in[26];
    const float* tmp_b2 = (const float*)d_in[27];
    const float* norm_g = (const float*)d_in[28];
    const float* norm_b = (const float*)d_in[29];
    float* out = (float*)d_out;

    float *Himp, *xi, *Hrsn, *reasoned, *Q, *K, *V, *attn, *proj, *part, *rmean, *temp, *xr;
    float *WtImp, *WtRsn1, *WtRsn2, *WtQ, *WtK, *WtV, *WtO;
    uint32_t* mbits;
    cudaGetSymbolAddress((void**)&Himp,     g_Himp);
    cudaGetSymbolAddress((void**)&xi,       g_xi);
    cudaGetSymbolAddress((void**)&Hrsn,     g_Hrsn);
    cudaGetSymbolAddress((void**)&reasoned, g_reasoned);
    cudaGetSymbolAddress((void**)&Q,        g_Q);
    cudaGetSymbolAddress((void**)&K,        g_K);
    cudaGetSymbolAddress((void**)&V,        g_V);
    cudaGetSymbolAddress((void**)&attn,     g_attn);
    cudaGetSymbolAddress((void**)&proj,     g_proj);
    cudaGetSymbolAddress((void**)&part,     g_part);
    cudaGetSymbolAddress((void**)&rmean,    g_rmean);
    cudaGetSymbolAddress((void**)&temp,     g_temp);
    cudaGetSymbolAddress((void**)&xr,       g_xr);
    cudaGetSymbolAddress((void**)&mbits,    g_mbits);
    cudaGetSymbolAddress((void**)&WtImp,    g_WtImp);
    cudaGetSymbolAddress((void**)&WtRsn1,   g_WtRsn1);
    cudaGetSymbolAddress((void**)&WtRsn2,   g_WtRsn2);
    cudaGetSymbolAddress((void**)&WtQ,      g_WtQ);
    cudaGetSymbolAddress((void**)&WtK,      g_WtK);
    cudaGetSymbolAddress((void**)&WtV,      g_WtV);
    cudaGetSymbolAddress((void**)&WtO,      g_WtO);

    cudaFuncSetAttribute(gemm_tf32, cudaFuncAttributeMaxDynamicSharedMemorySize, GSMEM_BYTES);
    cudaFuncSetAttribute(flash_wmma_kernel, cudaFuncAttributeMaxDynamicSharedMemorySize, ASM_BYTES);

    dim3 tb(32, 8);
    transpose_round<<<dim3(CH/32, Cz/32), tb>>>(imp_w1, WtImp, Cz, CH);
    transpose_round<<<dim3(Cz/32, Cz/32), tb>>>(rsn_w1, WtRsn1, Cz, Cz);
    transpose_round<<<dim3(Cz/32, Cz/32), tb>>>(rsn_w2, WtRsn2, Cz, Cz);
    transpose_round<<<dim3(Cz/32, Cz/32), tb>>>(q_w, WtQ, Cz, Cz);
    transpose_round<<<dim3(Cz/32, Cz/32), tb>>>(k_w, WtK, Cz, Cz);
    transpose_round<<<dim3(Cz/32, Cz/32), tb>>>(v_w, WtV, Cz, Cz);
    transpose_round<<<dim3(Cz/32, Cz/32), tb>>>(o_w, WtO, Cz, Cz);
    round_tf32_kernel<<<NT*Cz/256, 256>>>(x, xr);
    pack_mask_kernel<<<(int)((size_t)Bz*Tz*Tz/256), 256>>>(amask, mbits);

    // 1. importance net first linear
    gemm_tf32<<<dim3(CH/128, NT/128), 256, GSMEM_BYTES>>>(xr, WtImp, imp_b1, Himp, CH, 0);
    // 2. LN + GELU
    ln_gelu_kernel<CH><<<NT, 256>>>(Himp, imp_g, imp_be);
    // 3. gate
    gate_xi_kernel<<<NT, 256>>>(Himp, imp_w2, imp_b2, x, xi);
    // 4. reasoning first linear
    gemm_tf32<<<dim3(Cz/128, NT/128), 256, GSMEM_BYTES>>>(xi, WtRsn1, rsn_b1, Hrsn, Cz, 0);
    // 5. LN + GELU
    ln_gelu_kernel<Cz><<<NT, 256>>>(Hrsn, rsn_g, rsn_be);
    // 6. reasoning second linear (rounded: feeds q-proj)
    gemm_tf32<<<dim3(Cz/128, NT/128), 256, GSMEM_BYTES>>>(Hrsn, WtRsn2, rsn_b2, reasoned, Cz, 1);
    // 7. Q/K/V projections (rounded: feed wmma attention)
    gemm_tf32<<<dim3(Cz/128, NT/128), 256, GSMEM_BYTES>>>(reasoned, WtQ, q_b, Q, Cz, 1);
    gemm_tf32<<<dim3(Cz/128, NT/128), 256, GSMEM_BYTES>>>(xi,       WtK, k_b, K, Cz, 1);
    gemm_tf32<<<dim3(Cz/128, NT/128), 256, GSMEM_BYTES>>>(xr,       WtV, v_b, V, Cz, 1);
    // 8. column mean
    colmean_part<<<dim3(Cz/256, Bz, 8), 256>>>(reasoned, part);
    colmean_fin<<<dim3(Cz/256, Bz), 256>>>(part, rmean);
    // 9. temperature net
    temp_kernel<<<Bz, 512>>>(rmean, tmp_w1, tmp_b1, tmp_g, tmp_be, tmp_w2, tmp_b2, temp);
    // 10. attention (wmma tf32)
    flash_wmma_kernel<<<dim3(Tz/128, Hh, Bz), 256, ASM_BYTES>>>(Q, K, V, mbits, temp, attn);
    // 11. output projection
    gemm_tf32<<<dim3(Cz/128, NT/128), 256, GSMEM_BYTES>>>(attn, WtO, o_b, proj, Cz, 0);
    // 12. residual + LN
    resid_ln_kernel<<<NT, 256>>>(x, proj, norm_g, norm_b, out);
}

// round 11
// speedup vs baseline: 1.7009x; 1.0333x over previous
#include <cuda_runtime.h>
#include <cuda_bf16.h>
#include <math.h>
#include <cstdint>
#include <mma.h>

using namespace nvcuda;

// Problem constants
#define Bz 2
#define Tz 2048
#define Cz 1024
#define Hh 16
#define Dd 64
#define CH 512
#define NT (Bz*Tz)          // 4096 rows

// ---------------- scratch (device globals; no runtime alloc) ----------------
__device__ float g_Himp[NT*CH];
__device__ float g_xi[NT*Cz];
__device__ float g_Hrsn[NT*Cz];
__device__ float g_reasoned[NT*Cz];
__device__ float g_Q[NT*Cz];
__device__ float g_K[NT*Cz];
__device__ float g_V[NT*Cz];
__device__ float g_attn[NT*Cz];
__device__ float g_proj[NT*Cz];
__device__ float g_part[16*Cz];
__device__ float g_rmean[Bz*Cz];
__device__ float g_temp[Bz*Hh];
__device__ float g_xr[NT*Cz];          // x rounded to tf32
__device__ uint32_t g_mbits[(size_t)Bz*Tz*Tz/32];   // packed attention mask (1MB)
// transposed (N-major -> [N,K] K-contiguous) + tf32-rounded weights
__device__ float g_WtImp[CH*Cz];
__device__ float g_WtRsn1[Cz*Cz];
__device__ float g_WtRsn2[Cz*Cz];
__device__ float g_WtQ[Cz*Cz];
__device__ float g_WtK[Cz*Cz];
__device__ float g_WtV[Cz*Cz];
__device__ float g_WtO[Cz*Cz];

// ---------------- helpers ----------------
__device__ __forceinline__ uint32_t smem_to_u32(const void* p) {
    uint32_t a;
    asm("{ .reg .u64 t; cvta.to.shared.u64 t, %1; cvt.u32.u64 %0, t; }" : "=r"(a) : "l"(p));
    return a;
}
__device__ __forceinline__ float to_tf32(float f) {
    uint32_t u; asm("cvt.rna.tf32.f32 %0, %1;" : "=r"(u) : "f"(f));
    return __uint_as_float(u);
}
__device__ __forceinline__ void cp_async16(uint32_t dst, const void* src) {
    asm volatile("cp.async.cg.shared.global [%0], [%1], 16;" :: "r"(dst), "l"(src) : "memory");
}
__device__ __forceinline__ void cp_commit() { asm volatile("cp.async.commit_group;" ::: "memory"); }
template<int N> __device__ __forceinline__ void cp_wait() {
    asm volatile("cp.async.wait_group %0;" :: "n"(N) : "memory");
}

__device__ __forceinline__ float blockReduceSum(float v) {
    __shared__ float sh[32];
    int lane = threadIdx.x & 31, wid = threadIdx.x >> 5;
    #pragma unroll
    for (int o = 16; o; o >>= 1) v += __shfl_down_sync(0xffffffffu, v, o);
    if (lane == 0) sh[wid] = v;
    __syncthreads();
    int nw = blockDim.x >> 5;
    v = (threadIdx.x < nw) ? sh[threadIdx.x] : 0.f;
    if (wid == 0) {
        #pragma unroll
        for (int o = 16; o; o >>= 1) v += __shfl_down_sync(0xffffffffu, v, o);
        if (lane == 0) sh[0] = v;
    }
    __syncthreads();
    float r = sh[0];
    __syncthreads();
    return r;
}

__device__ __forceinline__ float gelu_exact(float x) {
    return 0.5f * x * (1.0f + erff(x * 0.70710678118654752f));
}

// ---------------- wmma tf32 GEMM core (3-stage cp.async pipeline) ----------------
#define GLD  36
#define GSTG (128*GLD)
#define GSTAGE_FLOATS (2*GSTG)
#define GNSTAGE 3
#define GSMEM_BYTES (GNSTAGE*GSTAGE_FLOATS*4)    // 110592 B; epilogue needs 67584 B
#define ELD 132

__device__ __forceinline__ void gemm_tf32_body(
    float* smf, uint32_t sb,
    const float* __restrict__ A, const float* __restrict__ Wt,
    const float* __restrict__ bias, float* __restrict__ C,
    int N, int round_out, int bx, int by)
{
    const int tid = threadIdx.x;
    const int wid = tid >> 5;
    const int wm = wid >> 2;
    const int wn = wid & 3;

    wmma::fragment<wmma::accumulator, 16, 16, 8, float> acc[4][2];
    #pragma unroll
    for (int mi = 0; mi < 4; mi++)
        #pragma unroll
        for (int ni = 0; ni < 2; ni++)
            wmma::fill_fragment(acc[mi][ni], 0.0f);

    const float* Abase = A  + (size_t)by * 128 * Cz;
    const float* Bbase = Wt + (size_t)bx * 128 * Cz;

    auto load_stage = [&](int s, int kc) {
        uint32_t ab = sb + (uint32_t)s * GSTAGE_FLOATS * 4;
        uint32_t bb = ab + GSTG * 4;
        #pragma unroll
        for (int i = 0; i < 4; i++) {
            int idx = i * 256 + tid;
            int r = idx >> 3, c = (idx & 7) * 4;
            uint32_t soff = (uint32_t)(r * GLD + c) * 4;
            cp_async16(ab + soff, Abase + (size_t)r * Cz + kc * 32 + c);
            cp_async16(bb + soff, Bbase + (size_t)r * Cz + kc * 32 + c);
        }
        cp_commit();
    };

    load_stage(0, 0);
    load_stage(1, 1);
    load_stage(2, 2);

    for (int kc = 0; kc < 32; kc++) {
        int s = kc % 3;
        if (kc < 30)       cp_wait<2>();
        else if (kc == 30) cp_wait<1>();
        else               cp_wait<0>();
        __syncthreads();

        const float* As = smf + s * GSTAGE_FLOATS;
        const float* Bs = As + GSTG;

        #pragma unroll
        for (int kk = 0; kk < 4; kk++) {
            wmma::fragment<wmma::matrix_a, 16, 16, 8, wmma::precision::tf32, wmma::row_major> af[4];
            wmma::fragment<wmma::matrix_b, 16, 16, 8, wmma::precision::tf32, wmma::col_major> bf[2];
            #pragma unroll
            for (int mi = 0; mi < 4; mi++)
                wmma::load_matrix_sync(af[mi], As + (wm * 64 + mi * 16) * GLD + kk * 8, GLD);
            #pragma unroll
            for (int ni = 0; ni < 2; ni++)
                wmma::load_matrix_sync(bf[ni], Bs + (wn * 32 + ni * 16) * GLD + kk * 8, GLD);
            #pragma unroll
            for (int mi = 0; mi < 4; mi++)
                #pragma unroll
                for (int ni = 0; ni < 2; ni++)
                    wmma::mma_sync(acc[mi][ni], af[mi], bf[ni], acc[mi][ni]);
        }
        __syncthreads();
        if (kc + 3 < 32) load_stage(s, kc + 3);
    }

    #pragma unroll
    for (int mi = 0; mi < 4; mi++)
        #pragma unroll
        for (int ni = 0; ni < 2; ni++)
            wmma::store_matrix_sync(smf + (wm * 64 + mi * 16) * ELD + wn * 32 + ni * 16,
                                    acc[mi][ni], ELD, wmma::mem_row_major);
    __syncthreads();

    #pragma unroll
    for (int i = 0; i < 16; i++) {
        int idx = i * 256 + tid;
        int r = idx >> 5, c = (idx & 31) * 4;
        const float* bp = bias + bx * 128 + c;
        float4 o;
        o.x = smf[r * ELD + c + 0] + bp[0];
        o.y = smf[r * ELD + c + 1] + bp[1];
        o.z = smf[r * ELD + c + 2] + bp[2];
        o.w = smf[r * ELD + c + 3] + bp[3];
        if (round_out) {
            o.x = to_tf32(o.x); o.y = to_tf32(o.y);
            o.z = to_tf32(o.z); o.w = to_tf32(o.w);
        }
        *(float4*)&C[(size_t)(by * 128 + r) * N + bx * 128 + c] = o;
    }
}

__global__ __launch_bounds__(256) void gemm_tf32(
    const float* __restrict__ A, const float* __restrict__ Wt,
    const float* __restrict__ bias, float* __restrict__ C,
    int N, int round_out)
{
    extern __shared__ float smf[];
    gemm_tf32_body(smf, smem_to_u32(smf), A, Wt, bias, C, N, round_out,
                   blockIdx.x, blockIdx.y);
}

// batched Q/K/V: blockIdx.z selects (input, weight, bias, output); all N=Cz, rounded
__global__ __launch_bounds__(256) void gemm_tf32_qkv(
    const float* __restrict__ Aq, const float* __restrict__ Ak, const float* __restrict__ Av,
    const float* __restrict__ Wq, const float* __restrict__ Wk, const float* __restrict__ Wv,
    const float* __restrict__ bq, const float* __restrict__ bk, const float* __restrict__ bv,
    float* __restrict__ Cq, float* __restrict__ Ck, float* __restrict__ Cv)
{
    extern __shared__ float smf[];
    const float* A; const float* W; const float* bb; float* C;
    if (blockIdx.z == 0)      { A = Aq; W = Wq; bb = bq; C = Cq; }
    else if (blockIdx.z == 1) { A = Ak; W = Wk; bb = bk; C = Ck; }
    else                      { A = Av; W = Wv; bb = bv; C = Cv; }
    gemm_tf32_body(smf, smem_to_u32(smf), A, W, bb, C, Cz, 1,
                   blockIdx.x, blockIdx.y);
}

// ---------------- batched transpose + round: 7 weights in one launch ----------------
struct TransArgs {
    const float* src[7];
    float* dst[7];
    int n[7];           // N (output rows of Wt); K is always Cz
};

__global__ void transpose_round_batch(TransArgs ta) {
    int z = blockIdx.z;
    int N = ta.n[z];
    int nb = blockIdx.x * 32, kb = blockIdx.y * 32;
    if (nb >= N) return;
    const float* W = ta.src[z];
    float* Wt = ta.dst[z];
    __shared__ float t[32][33];
    #pragma unroll
    for (int i = threadIdx.y; i < 32; i += 8)
        t[i][threadIdx.x] = W[(size_t)(kb + i) * N + nb + threadIdx.x];
    __syncthreads();
    #pragma unroll
    for (int i = threadIdx.y; i < 32; i += 8)
        Wt[(size_t)(nb + i) * Cz + kb + threadIdx.x] = to_tf32(t[threadIdx.x][i]);
}

__global__ void round_tf32_kernel(const float* __restrict__ in, float* __restrict__ out) {
    int i = blockIdx.x * 256 + threadIdx.x;
    out[i] = to_tf32(in[i]);
}

// ---------------- pack mask to bits (ballot) ----------------
__global__ void pack_mask_kernel(const int* __restrict__ mask, uint32_t* __restrict__ mbits) {
    size_t p = (size_t)blockIdx.x * 256 + threadIdx.x;
    unsigned bit = (mask[p] != 0) ? 1u : 0u;
    uint32_t w = __ballot_sync(0xffffffffu, bit);
    if ((threadIdx.x & 31) == 0) mbits[p >> 5] = w;
}

// ---------------- LN + GELU ----------------
template<int COLS>
__global__ __launch_bounds__(256) void ln_gelu_kernel(
    float* __restrict__ X, const float* __restrict__ g, const float* __restrict__ beta)
{
    const int row = blockIdx.x;
    float* xr = X + (size_t)row * COLS;
    constexpr int PT = COLS / 256;
    float v[PT];
    float s = 0.f;
    #pragma unroll
    for (int i = 0; i < PT; i++) { v[i] = xr[threadIdx.x + i * 256]; s += v[i]; }
    float mean = blockReduceSum(s) * (1.0f / COLS);
    float s2 = 0.f;
    #pragma unroll
    for (int i = 0; i < PT; i++) { float d = v[i] - mean; s2 += d * d; }
    float var = blockReduceSum(s2) * (1.0f / COLS);
    float rstd = rsqrtf(var + 1e-5f);
    #pragma unroll
    for (int i = 0; i < PT; i++) {
        int c = threadIdx.x + i * 256;
        float y = (v[i] - mean) * rstd * g[c] + beta[c];
        xr[c] = to_tf32(gelu_exact(y));
    }
}

// ---------------- importance gate ----------------
__global__ __launch_bounds__(256) void gate_xi_kernel(
    const float* __restrict__ H, const float* __restrict__ w2, const float* __restrict__ b2,
    const float* __restrict__ x, float* __restrict__ xi)
{
    const int row = blockIdx.x;
    float p = 0.f;
    const float* hr = H + (size_t)row * CH;
    for (int c = threadIdx.x; c < CH; c += 256) p += hr[c] * w2[c];
    float sum = blockReduceSum(p);
    float sg = 1.0f / (1.0f + expf(-(sum + b2[0])));
    float imp = fmaxf(sg, 1e-6f);
    const float* xr = x + (size_t)row * Cz;
    float* xo = xi + (size_t)row * Cz;
    for (int c = threadIdx.x; c < Cz; c += 256) xo[c] = to_tf32(xr[c] * imp);
}

// ---------------- column mean ----------------
__global__ void colmean_part(const float* __restrict__ R, float* __restrict__ part) {
    int c = blockIdx.x * 256 + threadIdx.x;
    int b = blockIdx.y;
    int ch = blockIdx.z;
    float s = 0.f;
    int t0 = ch * 256;
    for (int t = t0; t < t0 + 256; t++)
        s += R[((size_t)(b * Tz + t)) * Cz + c];
    part[(ch * Bz + b) * Cz + c] = s;
}
__global__ void colmean_fin(const float* __restrict__ part, float* __restrict__ out) {
    int c = blockIdx.x * 256 + threadIdx.x;
    int b = blockIdx.y;
    float s = 0.f;
    for (int ch = 0; ch < 8; ch++) s += part[(ch * Bz + b) * Cz + c];
    out[b * Cz + c] = s * (1.0f / Tz);
}

// ---------------- temperature net ----------------
__global__ __launch_bounds__(512) void temp_kernel(
    const float* __restrict__ rmean,
    const float* __restrict__ w1, const float* __restrict__ b1,
    const float* __restrict__ g, const float* __restrict__ beta,
    const float* __restrict__ w2, const float* __restrict__ b2,
    float* __restrict__ temp)
{
    const int b = blockIdx.x;
    const int tid = threadIdx.x;
    __shared__ float hsm[CH];
    const float* xr = rmean + b * Cz;
    float acc = b1[tid];
    for (int k = 0; k < Cz; k++) acc = fmaf(xr[k], w1[k * CH + tid], acc);
    float mean = blockReduceSum(acc) * (1.0f / CH);
    float d = acc - mean;
    float var = blockReduceSum(d * d) * (1.0f / CH);
    float rstd = rsqrtf(var + 1e-5f);
    float y = d * rstd * g[tid] + beta[tid];
    hsm[tid] = gelu_exact(y);
    __syncthreads();
    if (tid < Hh) {
        float a2 = b2[tid];
        for (int k = 0; k < CH; k++) a2 = fmaf(hsm[k], w2[k * Hh + tid], a2);
        float sp = (a2 > 20.f) ? a2 : log1pf(expf(a2));
        temp[b * Hh + tid] = sp + 0.5f;
    }
}

// ---------------- wmma tf32 flash attention ----------------
#define AQS 0
#define AKS 8704
#define AVS 17408
#define ASS 25600
#define AOS 42496
#define AMS 51200
#define ALS 51328
#define ACS 51456
#define ASM_FLOATS 51584
#define ASM_BYTES (ASM_FLOATS*4)

__global__ __launch_bounds__(256) void flash_wmma_kernel(
    const float* __restrict__ Q, const float* __restrict__ Kp,
    const float* __restrict__ Vp, const uint32_t* __restrict__ mbits,
    const float* __restrict__ temp, float* __restrict__ O)
{
    extern __shared__ float smf[];
    uint32_t sb = smem_to_u32(smf);
    const int tid = threadIdx.x;
    const int wid = tid >> 5;
    const int wm = wid >> 2;          // 0..1
    const int wn = wid & 3;           // 0..3
    const int qt = blockIdx.x, h = blockIdx.y, b = blockIdx.z;
    const int qrow0 = qt * 128;
    const float sc = 0.125f * temp[b * Hh + h];

    #pragma unroll
    for (int i = 0; i < 8; i++) {
        int idx = i * 256 + tid;
        int r = idx >> 4, c4 = (idx & 15) * 4;
        float4 qv = *(const float4*)(Q + ((size_t)(b * Tz + qrow0 + r)) * Cz + h * Dd + c4);
        *(float4*)&smf[AQS + r * 68 + c4] = qv;
    }
    if (tid < 128) { smf[AMS + tid] = -1e30f; smf[ALS + tid] = 0.f; }

    auto load_K = [&](int k0) {
        #pragma unroll
        for (int i = 0; i < 8; i++) {
            int idx = i * 256 + tid;
            int r = idx >> 4, c4 = (idx & 15) * 4;
            cp_async16(sb + (AKS + r * 68 + c4) * 4,
                       Kp + ((size_t)(b * Tz + k0 + r)) * Cz + h * Dd + c4);
        }
        cp_commit();
    };
    auto load_V = [&](int k0) {
        #pragma unroll
        for (int i = 0; i < 8; i++) {
            int idx = i * 256 + tid;
            int r = idx >> 4, c4 = (idx & 15) * 4;
            cp_async16(sb + (AVS + r * 64 + c4) * 4,
                       Vp + ((size_t)(b * Tz + k0 + r)) * Cz + h * Dd + c4);
        }
        cp_commit();
    };

    load_K(0);
    load_V(0);
    __syncthreads();

    const int NBLK = Tz / 128;   // 16
    for (int blk = 0; blk < NBLK; blk++) {
        int k0 = blk * 128;
        cp_wait<1>();
        __syncthreads();

        // ---- S = Q @ K^T ----
        {
            wmma::fragment<wmma::accumulator, 16, 16, 8, float> acc[4][2];
            #pragma unroll
            for (int mi = 0; mi < 4; mi++)
                #pragma unroll
                for (int ni = 0; ni < 2; ni++)
                    wmma::fill_fragment(acc[mi][ni], 0.0f);
            #pragma unroll
            for (int kk = 0; kk < 8; kk++) {
                wmma::fragment<wmma::matrix_a, 16, 16, 8, wmma::precision::tf32, wmma::row_major> af[4];
                wmma::fragment<wmma::matrix_b, 16, 16, 8, wmma::precision::tf32, wmma::col_major> bf[2];
                #pragma unroll
                for (int mi = 0; mi < 4; mi++)
                    wmma::load_matrix_sync(af[mi], smf + AQS + (wm * 64 + mi * 16) * 68 + kk * 8, 68);
                #pragma unroll
                for (int ni = 0; ni < 2; ni++)
                    wmma::load_matrix_sync(bf[ni], smf + AKS + (wn * 32 + ni * 16) * 68 + kk * 8, 68);
                #pragma unroll
                for (int mi = 0; mi < 4; mi++)
                    #pragma unroll
                    for (int ni = 0; ni < 2; ni++)
                        wmma::mma_sync(acc[mi][ni], af[mi], bf[ni], acc[mi][ni]);
            }
            #pragma unroll
            for (int mi = 0; mi < 4; mi++)
                #pragma unroll
                for (int ni = 0; ni < 2; ni++)
                    wmma::store_matrix_sync(smf + ASS + (wm * 64 + mi * 16) * 132 + wn * 32 + ni * 16,
                                            acc[mi][ni], 132, wmma::mem_row_major);
        }
        __syncthreads();

        if (blk + 1 < NBLK) load_K(k0 + 128);

        // ---- online softmax ----
        {
            int r = tid >> 1, c0 = (tid & 1) * 64;
            size_t mb_idx = (((size_t)(b * Tz + qrow0 + r)) * Tz + k0 + c0) >> 5;
            uint32_t w0 = mbits[mb_idx], w1 = mbits[mb_idx + 1];
            uint64_t mw = (uint64_t)w0 | ((uint64_t)w1 << 32);
            float* Srow = smf + ASS + r * 132 + c0;
            float vmax = -1e30f;
            #pragma unroll
            for (int j = 0; j < 64; j++) {
                float s = Srow[j];
                s = ((mw >> j) & 1ull) ? s * sc : -1e30f;
                Srow[j] = s;
                vmax = fmaxf(vmax, s);
            }
            vmax = fmaxf(vmax, __shfl_xor_sync(0xffffffffu, vmax, 1));
            float mold = smf[AMS + r];
            float mnew = fmaxf(mold, vmax);
            float corr = __expf(mold - mnew);
            float lsum = 0.f;
            #pragma unroll
            for (int j = 0; j < 64; j++) {
                float p = __expf(Srow[j] - mnew);
                lsum += p;
                Srow[j] = to_tf32(p);
            }
            lsum += __shfl_xor_sync(0xffffffffu, lsum, 1);
            if ((tid & 1) == 0) {
                smf[AMS + r] = mnew;
                smf[ALS + r] = smf[ALS + r] * corr + lsum;
                smf[ACS + r] = corr;
            }
        }

        if (blk + 1 < NBLK) cp_wait<1>(); else cp_wait<0>();
        __syncthreads();

        // ---- PV = P @ V ----
        {
            wmma::fragment<wmma::accumulator, 16, 16, 8, float> acc2[4];
            #pragma unroll
            for (int mi = 0; mi < 4; mi++) wmma::fill_fragment(acc2[mi], 0.0f);
            #pragma unroll
            for (int kk = 0; kk < 16; kk++) {
                wmma::fragment<wmma::matrix_b, 16, 16, 8, wmma::precision::tf32, wmma::row_major> bf;
                wmma::load_matrix_sync(bf, smf + AVS + (kk * 8) * 64 + wn * 16, 64);
                #pragma unroll
                for (int mi = 0; mi < 4; mi++) {
                    wmma::fragment<wmma::matrix_a, 16, 16, 8, wmma::precision::tf32, wmma::row_major> af;
                    wmma::load_matrix_sync(af, smf + ASS + (wm * 64 + mi * 16) * 132 + kk * 8, 132);
                    wmma::mma_sync(acc2[mi], af, bf, acc2[mi]);
                }
            }
            __syncthreads();
            #pragma unroll
            for (int mi = 0; mi < 4; mi++)
                wmma::store_matrix_sync(smf + ASS + (wm * 64 + mi * 16) * 132 + wn * 16,
                                        acc2[mi], 132, wmma::mem_row_major);
        }

        if (blk + 1 < NBLK) load_V(k0 + 128);
        __syncthreads();

        // ---- merge into O ----
        if (blk == 0) {
            #pragma unroll
            for (int i = 0; i < 32; i++) {
                int idx = i * 256 + tid;
                int r = idx >> 6, c = idx & 63;
                smf[AOS + r * 68 + c] = smf[ASS + r * 132 + c];
            }
        } else {
            #pragma unroll
            for (int i = 0; i < 32; i++) {
                int idx = i * 256 + tid;
                int r = idx >> 6, c = idx & 63;
                smf[AOS + r * 68 + c] = smf[AOS + r * 68 + c] * smf[ACS + r] + smf[ASS + r * 132 + c];
            }
        }
        __syncthreads();
    }

    #pragma unroll
    for (int i = 0; i < 32; i++) {
        int idx = i * 256 + tid;
        int r = idx >> 6, c = idx & 63;
        float val = smf[AOS + r * 68 + c] / smf[ALS + r];
        O[((size_t)(b * Tz + qrow0 + r)) * Cz + h * Dd + c] = to_tf32(val);
    }
}

// ---------------- residual + LayerNorm epilogue ----------------
__global__ __launch_bounds__(256) void resid_ln_kernel(
    const float* __restrict__ x, const float* __restrict__ p,
    const float* __restrict__ g, const float* __restrict__ beta,
    float* __restrict__ out)
{
    const int row = blockIdx.x;
    const float* xr = x + (size_t)row * Cz;
    const float* pr = p + (size_t)row * Cz;
    float v[4];
    float s = 0.f;
    #pragma unroll
    for (int i = 0; i < 4; i++) {
        int c = threadIdx.x + i * 256;
        v[i] = xr[c] + pr[c];
        s += v[i];
    }
    float mean = blockReduceSum(s) * (1.0f / Cz);
    float s2 = 0.f;
    #pragma unroll
    for (int i = 0; i < 4; i++) { float d = v[i] - mean; s2 += d * d; }
    float var = blockReduceSum(s2) * (1.0f / Cz);
    float rstd = rsqrtf(var + 1e-5f);
    #pragma unroll
    for (int i = 0; i < 4; i++) {
        int c = threadIdx.x + i * 256;
        out[(size_t)row * Cz + c] = (v[i] - mean) * rstd * g[c] + beta[c];
    }
}

// ---------------- launch ----------------
extern "C" void kernel_launch(void* const* d_in, const int* in_sizes, int n_in,
                              void* d_out, int out_size)
{
    const float* x      = (const float*)d_in[0];
    const int*   amask  = (const int*)  d_in[1];
    const float* imp_w1 = (const float*)d_in[2];
    const float* imp_b1 = (const float*)d_in[3];
    const float* imp_g  = (const float*)d_in[4];
    const float* imp_be = (const float*)d_in[5];
    const float* imp_w2 = (const float*)d_in[6];
    const float* imp_b2 = (const float*)d_in[7];
    const float* rsn_w1 = (const float*)d_in[8];
    const float* rsn_b1 = (const float*)d_in[9];
    const float* rsn_g  = (const float*)d_in[10];
    const float* rsn_be = (const float*)d_in[11];
    const float* rsn_w2 = (const float*)d_in[12];
    const float* rsn_b2 = (const float*)d_in[13];
    const float* q_w    = (const float*)d_in[14];
    const float* q_b    = (const float*)d_in[15];
    const float* k_w    = (const float*)d_in[16];
    const float* k_b    = (const float*)d_in[17];
    const float* v_w    = (const float*)d_in[18];
    const float* v_b    = (const float*)d_in[19];
    const float* o_w    = (const float*)d_in[20];
    const float* o_b    = (const float*)d_in[21];
    const float* tmp_w1 = (const float*)d_in[22];
    const float* tmp_b1 = (const float*)d_in[23];
    const float* tmp_g  = (const float*)d_in[24];
    const float* tmp_be = (const float*)d_in[25];
    const float* tmp_w2 = (const float*)d_in[26];
    const float* tmp_b2 = (const float*)d_in[27];
    const float* norm_g = (const float*)d_in[28];
    const float* norm_b = (const float*)d_in[29];
    float* out = (float*)d_out;

    float *Himp, *xi, *Hrsn, *reasoned, *Q, *K, *V, *attn, *proj, *part, *rmean, *temp, *xr;
    float *WtImp, *WtRsn1, *WtRsn2, *WtQ, *WtK, *WtV, *WtO;
    uint32_t* mbits;
    cudaGetSymbolAddress((void**)&Himp,     g_Himp);
    cudaGetSymbolAddress((void**)&xi,       g_xi);
    cudaGetSymbolAddress((void**)&Hrsn,     g_Hrsn);
    cudaGetSymbolAddress((void**)&reasoned, g_reasoned);
    cudaGetSymbolAddress((void**)&Q,        g_Q);
    cudaGetSymbolAddress((void**)&K,        g_K);
    cudaGetSymbolAddress((void**)&V,        g_V);
    cudaGetSymbolAddress((void**)&attn,     g_attn);
    cudaGetSymbolAddress((void**)&proj,     g_proj);
    cudaGetSymbolAddress((void**)&part,     g_part);
    cudaGetSymbolAddress((void**)&rmean,    g_rmean);
    cudaGetSymbolAddress((void**)&temp,     g_temp);
    cudaGetSymbolAddress((void**)&xr,       g_xr);
    cudaGetSymbolAddress((void**)&mbits,    g_mbits);
    cudaGetSymbolAddress((void**)&WtImp,    g_WtImp);
    cudaGetSymbolAddress((void**)&WtRsn1,   g_WtRsn1);
    cudaGetSymbolAddress((void**)&WtRsn2,   g_WtRsn2);
    cudaGetSymbolAddress((void**)&WtQ,      g_WtQ);
    cudaGetSymbolAddress((void**)&WtK,      g_WtK);
    cudaGetSymbolAddress((void**)&WtV,      g_WtV);
    cudaGetSymbolAddress((void**)&WtO,      g_WtO);

    cudaFuncSetAttribute(gemm_tf32, cudaFuncAttributeMaxDynamicSharedMemorySize, GSMEM_BYTES);
    cudaFuncSetAttribute(gemm_tf32_qkv, cudaFuncAttributeMaxDynamicSharedMemorySize, GSMEM_BYTES);
    cudaFuncSetAttribute(flash_wmma_kernel, cudaFuncAttributeMaxDynamicSharedMemorySize, ASM_BYTES);

    // batched weight transposes (+ tf32 rounding)
    TransArgs ta;
    ta.src[0] = imp_w1; ta.dst[0] = WtImp;  ta.n[0] = CH;
    ta.src[1] = rsn_w1; ta.dst[1] = WtRsn1; ta.n[1] = Cz;
    ta.src[2] = rsn_w2; ta.dst[2] = WtRsn2; ta.n[2] = Cz;
    ta.src[3] = q_w;    ta.dst[3] = WtQ;    ta.n[3] = Cz;
    ta.src[4] = k_w;    ta.dst[4] = WtK;    ta.n[4] = Cz;
    ta.src[5] = v_w;    ta.dst[5] = WtV;    ta.n[5] = Cz;
    ta.src[6] = o_w;    ta.dst[6] = WtO;    ta.n[6] = Cz;
    transpose_round_batch<<<dim3(32, 32, 7), dim3(32, 8)>>>(ta);
    round_tf32_kernel<<<NT*Cz/256, 256>>>(x, xr);
    pack_mask_kernel<<<(int)((size_t)Bz*Tz*Tz/256), 256>>>(amask, mbits);

    // 1. importance net first linear
    gemm_tf32<<<dim3(CH/128, NT/128), 256, GSMEM_BYTES>>>(xr, WtImp, imp_b1, Himp, CH, 0);
    // 2. LN + GELU
    ln_gelu_kernel<CH><<<NT, 256>>>(Himp, imp_g, imp_be);
    // 3. gate
    gate_xi_kernel<<<NT, 256>>>(Himp, imp_w2, imp_b2, x, xi);
    // 4. reasoning first linear
    gemm_tf32<<<dim3(Cz/128, NT/128), 256, GSMEM_BYTES>>>(xi, WtRsn1, rsn_b1, Hrsn, Cz, 0);
    // 5. LN + GELU
    ln_gelu_kernel<Cz><<<NT, 256>>>(Hrsn, rsn_g, rsn_be);
    // 6. reasoning second linear (rounded: feeds q-proj)
    gemm_tf32<<<dim3(Cz/128, NT/128), 256, GSMEM_BYTES>>>(Hrsn, WtRsn2, rsn_b2, reasoned, Cz, 1);
    // 7. Q/K/V projections batched (rounded: feed wmma attention)
    gemm_tf32_qkv<<<dim3(Cz/128, NT/128, 3), 256, GSMEM_BYTES>>>(
        reasoned, xi, xr, WtQ, WtK, WtV, q_b, k_b, v_b, Q, K, V);
    // 8. column mean
    colmean_part<<<dim3(Cz/256, Bz, 8), 256>>>(reasoned, part);
    colmean_fin<<<dim3(Cz/256, Bz), 256>>>(part, rmean);
    // 9. temperature net
    temp_kernel<<<Bz, 512>>>(rmean, tmp_w1, tmp_b1, tmp_g, tmp_be, tmp_w2, tmp_b2, temp);
    // 10. attention (wmma tf32)
    flash_wmma_kernel<<<dim3(Tz/128, Hh, Bz), 256, ASM_BYTES>>>(Q, K, V, mbits, temp, attn);
    // 11. output projection
    gemm_tf32<<<dim3(Cz/128, NT/128), 256, GSMEM_BYTES>>>(attn, WtO, o_b, proj, Cz, 0);
    // 12. residual + LN
    resid_ln_kernel<<<NT, 256>>>(x, proj, norm_g, norm_b, out);
}

// round 12
// speedup vs baseline: 1.7204x; 1.0114x over previous
#include <cuda_runtime.h>
#include <cuda_bf16.h>
#include <math.h>
#include <cstdint>
#include <mma.h>

using namespace nvcuda;

// Problem constants
#define Bz 2
#define Tz 2048
#define Cz 1024
#define Hh 16
#define Dd 64
#define CH 512
#define NT (Bz*Tz)          // 4096 rows

// ---------------- scratch (device globals; no runtime alloc) ----------------
__device__ float g_Himp[NT*CH];
__device__ float g_xi[NT*Cz];
__device__ float g_Hrsn[NT*Cz];
__device__ float g_reasoned[NT*Cz];
__device__ float g_Q[NT*Cz];
__device__ float g_K[NT*Cz];
__device__ float g_V[NT*Cz];
__device__ float g_attn[NT*Cz];
__device__ float g_proj[NT*Cz];
__device__ float g_part[16*Cz];
__device__ float g_rmean[Bz*Cz];
__device__ float g_temp[Bz*Hh];
__device__ float g_xr[NT*Cz];          // x rounded to tf32
__device__ uint32_t g_mbits[(size_t)Bz*Tz*Tz/32];   // packed attention mask (1MB)
// transposed (N-major -> [N,K] K-contiguous) + tf32-rounded weights
__device__ float g_WtImp[CH*Cz];
__device__ float g_WtRsn1[Cz*Cz];
__device__ float g_WtRsn2[Cz*Cz];
__device__ float g_WtQ[Cz*Cz];
__device__ float g_WtK[Cz*Cz];
__device__ float g_WtV[Cz*Cz];
__device__ float g_WtO[Cz*Cz];

// ---------------- helpers ----------------
__device__ __forceinline__ uint32_t smem_to_u32(const void* p) {
    uint32_t a;
    asm("{ .reg .u64 t; cvta.to.shared.u64 t, %1; cvt.u32.u64 %0, t; }" : "=r"(a) : "l"(p));
    return a;
}
__device__ __forceinline__ float to_tf32(float f) {
    uint32_t u; asm("cvt.rna.tf32.f32 %0, %1;" : "=r"(u) : "f"(f));
    return __uint_as_float(u);
}
__device__ __forceinline__ void cp_async16(uint32_t dst, const void* src) {
    asm volatile("cp.async.cg.shared.global [%0], [%1], 16;" :: "r"(dst), "l"(src) : "memory");
}
__device__ __forceinline__ void cp_commit() { asm volatile("cp.async.commit_group;" ::: "memory"); }
template<int N> __device__ __forceinline__ void cp_wait() {
    asm volatile("cp.async.wait_group %0;" :: "n"(N) : "memory");
}

__device__ __forceinline__ float blockReduceSum(float v) {
    __shared__ float sh[32];
    int lane = threadIdx.x & 31, wid = threadIdx.x >> 5;
    #pragma unroll
    for (int o = 16; o; o >>= 1) v += __shfl_down_sync(0xffffffffu, v, o);
    if (lane == 0) sh[wid] = v;
    __syncthreads();
    int nw = blockDim.x >> 5;
    v = (threadIdx.x < nw) ? sh[threadIdx.x] : 0.f;
    if (wid == 0) {
        #pragma unroll
        for (int o = 16; o; o >>= 1) v += __shfl_down_sync(0xffffffffu, v, o);
        if (lane == 0) sh[0] = v;
    }
    __syncthreads();
    float r = sh[0];
    __syncthreads();
    return r;
}

__device__ __forceinline__ float gelu_exact(float x) {
    return 0.5f * x * (1.0f + erff(x * 0.70710678118654752f));
}

// ---------------- wmma tf32 GEMM core (3-stage cp.async pipeline) ----------------
#define GLD  36
#define GSTG (128*GLD)
#define GSTAGE_FLOATS (2*GSTG)
#define GNSTAGE 3
#define GSMEM_BYTES (GNSTAGE*GSTAGE_FLOATS*4)    // 110592 B; 2 CTAs = 221184 <= 228KB carveout
#define ELD 132

__device__ __forceinline__ void gemm_tf32_body(
    float* smf, uint32_t sb,
    const float* __restrict__ A, const float* __restrict__ Wt,
    const float* __restrict__ bias, float* __restrict__ C,
    int N, int round_out, int bx, int by)
{
    const int tid = threadIdx.x;
    const int wid = tid >> 5;
    const int wm = wid >> 2;
    const int wn = wid & 3;

    wmma::fragment<wmma::accumulator, 16, 16, 8, float> acc[4][2];
    #pragma unroll
    for (int mi = 0; mi < 4; mi++)
        #pragma unroll
        for (int ni = 0; ni < 2; ni++)
            wmma::fill_fragment(acc[mi][ni], 0.0f);

    const float* Abase = A  + (size_t)by * 128 * Cz;
    const float* Bbase = Wt + (size_t)bx * 128 * Cz;

    auto load_stage = [&](int s, int kc) {
        uint32_t ab = sb + (uint32_t)s * GSTAGE_FLOATS * 4;
        uint32_t bb = ab + GSTG * 4;
        #pragma unroll
        for (int i = 0; i < 4; i++) {
            int idx = i * 256 + tid;
            int r = idx >> 3, c = (idx & 7) * 4;
            uint32_t soff = (uint32_t)(r * GLD + c) * 4;
            cp_async16(ab + soff, Abase + (size_t)r * Cz + kc * 32 + c);
            cp_async16(bb + soff, Bbase + (size_t)r * Cz + kc * 32 + c);
        }
        cp_commit();
    };

    load_stage(0, 0);
    load_stage(1, 1);
    load_stage(2, 2);

    for (int kc = 0; kc < 32; kc++) {
        int s = kc % 3;
        if (kc < 30)       cp_wait<2>();
        else if (kc == 30) cp_wait<1>();
        else               cp_wait<0>();
        __syncthreads();

        const float* As = smf + s * GSTAGE_FLOATS;
        const float* Bs = As + GSTG;

        #pragma unroll
        for (int kk = 0; kk < 4; kk++) {
            wmma::fragment<wmma::matrix_a, 16, 16, 8, wmma::precision::tf32, wmma::row_major> af[4];
            wmma::fragment<wmma::matrix_b, 16, 16, 8, wmma::precision::tf32, wmma::col_major> bf[2];
            #pragma unroll
            for (int mi = 0; mi < 4; mi++)
                wmma::load_matrix_sync(af[mi], As + (wm * 64 + mi * 16) * GLD + kk * 8, GLD);
            #pragma unroll
            for (int ni = 0; ni < 2; ni++)
                wmma::load_matrix_sync(bf[ni], Bs + (wn * 32 + ni * 16) * GLD + kk * 8, GLD);
            #pragma unroll
            for (int mi = 0; mi < 4; mi++)
                #pragma unroll
                for (int ni = 0; ni < 2; ni++)
                    wmma::mma_sync(acc[mi][ni], af[mi], bf[ni], acc[mi][ni]);
        }
        __syncthreads();
        if (kc + 3 < 32) load_stage(s, kc + 3);
    }

    #pragma unroll
    for (int mi = 0; mi < 4; mi++)
        #pragma unroll
        for (int ni = 0; ni < 2; ni++)
            wmma::store_matrix_sync(smf + (wm * 64 + mi * 16) * ELD + wn * 32 + ni * 16,
                                    acc[mi][ni], ELD, wmma::mem_row_major);
    __syncthreads();

    #pragma unroll
    for (int i = 0; i < 16; i++) {
        int idx = i * 256 + tid;
        int r = idx >> 5, c = (idx & 31) * 4;
        const float* bp = bias + bx * 128 + c;
        float4 o;
        o.x = smf[r * ELD + c + 0] + bp[0];
        o.y = smf[r * ELD + c + 1] + bp[1];
        o.z = smf[r * ELD + c + 2] + bp[2];
        o.w = smf[r * ELD + c + 3] + bp[3];
        if (round_out) {
            o.x = to_tf32(o.x); o.y = to_tf32(o.y);
            o.z = to_tf32(o.z); o.w = to_tf32(o.w);
        }
        *(float4*)&C[(size_t)(by * 128 + r) * N + bx * 128 + c] = o;
    }
}

__global__ __launch_bounds__(256, 2) void gemm_tf32(
    const float* __restrict__ A, const float* __restrict__ Wt,
    const float* __restrict__ bias, float* __restrict__ C,
    int N, int round_out)
{
    extern __shared__ float smf[];
    gemm_tf32_body(smf, smem_to_u32(smf), A, Wt, bias, C, N, round_out,
                   blockIdx.x, blockIdx.y);
}

// batched Q/K/V: blockIdx.z selects (input, weight, bias, output); all N=Cz, rounded
__global__ __launch_bounds__(256, 2) void gemm_tf32_qkv(
    const float* __restrict__ Aq, const float* __restrict__ Ak, const float* __restrict__ Av,
    const float* __restrict__ Wq, const float* __restrict__ Wk, const float* __restrict__ Wv,
    const float* __restrict__ bq, const float* __restrict__ bk, const float* __restrict__ bv,
    float* __restrict__ Cq, float* __restrict__ Ck, float* __restrict__ Cv)
{
    extern __shared__ float smf[];
    const float* A; const float* W; const float* bb; float* C;
    if (blockIdx.z == 0)      { A = Aq; W = Wq; bb = bq; C = Cq; }
    else if (blockIdx.z == 1) { A = Ak; W = Wk; bb = bk; C = Ck; }
    else                      { A = Av; W = Wv; bb = bv; C = Cv; }
    gemm_tf32_body(smf, smem_to_u32(smf), A, W, bb, C, Cz, 1,
                   blockIdx.x, blockIdx.y);
}

// ---------------- batched transpose + round: 7 weights in one launch ----------------
struct TransArgs {
    const float* src[7];
    float* dst[7];
    int n[7];           // N (output rows of Wt); K is always Cz
};

__global__ void transpose_round_batch(TransArgs ta) {
    int z = blockIdx.z;
    int N = ta.n[z];
    int nb = blockIdx.x * 32, kb = blockIdx.y * 32;
    if (nb >= N) return;
    const float* W = ta.src[z];
    float* Wt = ta.dst[z];
    __shared__ float t[32][33];
    #pragma unroll
    for (int i = threadIdx.y; i < 32; i += 8)
        t[i][threadIdx.x] = W[(size_t)(kb + i) * N + nb + threadIdx.x];
    __syncthreads();
    #pragma unroll
    for (int i = threadIdx.y; i < 32; i += 8)
        Wt[(size_t)(nb + i) * Cz + kb + threadIdx.x] = to_tf32(t[threadIdx.x][i]);
}

__global__ void round_tf32_kernel(const float* __restrict__ in, float* __restrict__ out) {
    int i = blockIdx.x * 256 + threadIdx.x;
    out[i] = to_tf32(in[i]);
}

// ---------------- pack mask to bits (ballot) ----------------
__global__ void pack_mask_kernel(const int* __restrict__ mask, uint32_t* __restrict__ mbits) {
    size_t p = (size_t)blockIdx.x * 256 + threadIdx.x;
    unsigned bit = (mask[p] != 0) ? 1u : 0u;
    uint32_t w = __ballot_sync(0xffffffffu, bit);
    if ((threadIdx.x & 31) == 0) mbits[p >> 5] = w;
}

// ---------------- LN + GELU ----------------
template<int COLS>
__global__ __launch_bounds__(256) void ln_gelu_kernel(
    float* __restrict__ X, const float* __restrict__ g, const float* __restrict__ beta)
{
    const int row = blockIdx.x;
    float* xr = X + (size_t)row * COLS;
    constexpr int PT = COLS / 256;
    float v[PT];
    float s = 0.f;
    #pragma unroll
    for (int i = 0; i < PT; i++) { v[i] = xr[threadIdx.x + i * 256]; s += v[i]; }
    float mean = blockReduceSum(s) * (1.0f / COLS);
    float s2 = 0.f;
    #pragma unroll
    for (int i = 0; i < PT; i++) { float d = v[i] - mean; s2 += d * d; }
    float var = blockReduceSum(s2) * (1.0f / COLS);
    float rstd = rsqrtf(var + 1e-5f);
    #pragma unroll
    for (int i = 0; i < PT; i++) {
        int c = threadIdx.x + i * 256;
        float y = (v[i] - mean) * rstd * g[c] + beta[c];
        xr[c] = to_tf32(gelu_exact(y));
    }
}

// ---------------- importance gate ----------------
__global__ __launch_bounds__(256) void gate_xi_kernel(
    const float* __restrict__ H, const float* __restrict__ w2, const float* __restrict__ b2,
    const float* __restrict__ x, float* __restrict__ xi)
{
    const int row = blockIdx.x;
    float p = 0.f;
    const float* hr = H + (size_t)row * CH;
    for (int c = threadIdx.x; c < CH; c += 256) p += hr[c] * w2[c];
    float sum = blockReduceSum(p);
    float sg = 1.0f / (1.0f + expf(-(sum + b2[0])));
    float imp = fmaxf(sg, 1e-6f);
    const float* xr = x + (size_t)row * Cz;
    float* xo = xi + (size_t)row * Cz;
    for (int c = threadIdx.x; c < Cz; c += 256) xo[c] = to_tf32(xr[c] * imp);
}

// ---------------- column mean ----------------
__global__ void colmean_part(const float* __restrict__ R, float* __restrict__ part) {
    int c = blockIdx.x * 256 + threadIdx.x;
    int b = blockIdx.y;
    int ch = blockIdx.z;
    float s = 0.f;
    int t0 = ch * 256;
    for (int t = t0; t < t0 + 256; t++)
        s += R[((size_t)(b * Tz + t)) * Cz + c];
    part[(ch * Bz + b) * Cz + c] = s;
}
__global__ void colmean_fin(const float* __restrict__ part, float* __restrict__ out) {
    int c = blockIdx.x * 256 + threadIdx.x;
    int b = blockIdx.y;
    float s = 0.f;
    for (int ch = 0; ch < 8; ch++) s += part[(ch * Bz + b) * Cz + c];
    out[b * Cz + c] = s * (1.0f / Tz);
}

// ---------------- temperature net ----------------
__global__ __launch_bounds__(512) void temp_kernel(
    const float* __restrict__ rmean,
    const float* __restrict__ w1, const float* __restrict__ b1,
    const float* __restrict__ g, const float* __restrict__ beta,
    const float* __restrict__ w2, const float* __restrict__ b2,
    float* __restrict__ temp)
{
    const int b = blockIdx.x;
    const int tid = threadIdx.x;
    __shared__ float hsm[CH];
    const float* xr = rmean + b * Cz;
    float acc = b1[tid];
    for (int k = 0; k < Cz; k++) acc = fmaf(xr[k], w1[k * CH + tid], acc);
    float mean = blockReduceSum(acc) * (1.0f / CH);
    float d = acc - mean;
    float var = blockReduceSum(d * d) * (1.0f / CH);
    float rstd = rsqrtf(var + 1e-5f);
    float y = d * rstd * g[tid] + beta[tid];
    hsm[tid] = gelu_exact(y);
    __syncthreads();
    if (tid < Hh) {
        float a2 = b2[tid];
        for (int k = 0; k < CH; k++) a2 = fmaf(hsm[k], w2[k * Hh + tid], a2);
        float sp = (a2 > 20.f) ? a2 : log1pf(expf(a2));
        temp[b * Hh + tid] = sp + 0.5f;
    }
}

// ---------------- wmma tf32 flash attention ----------------
#define AQS 0
#define AKS 8704
#define AVS 17408
#define ASS 25600
#define AOS 42496
#define AMS 51200
#define ALS 51328
#define ACS 51456
#define ASM_FLOATS 51584
#define ASM_BYTES (ASM_FLOATS*4)

__global__ __launch_bounds__(256) void flash_wmma_kernel(
    const float* __restrict__ Q, const float* __restrict__ Kp,
    const float* __restrict__ Vp, const uint32_t* __restrict__ mbits,
    const float* __restrict__ temp, float* __restrict__ O)
{
    extern __shared__ float smf[];
    uint32_t sb = smem_to_u32(smf);
    const int tid = threadIdx.x;
    const int wid = tid >> 5;
    const int wm = wid >> 2;          // 0..1
    const int wn = wid & 3;           // 0..3
    const int qt = blockIdx.x, h = blockIdx.y, b = blockIdx.z;
    const int qrow0 = qt * 128;
    const float sc = 0.125f * temp[b * Hh + h];

    #pragma unroll
    for (int i = 0; i < 8; i++) {
        int idx = i * 256 + tid;
        int r = idx >> 4, c4 = (idx & 15) * 4;
        float4 qv = *(const float4*)(Q + ((size_t)(b * Tz + qrow0 + r)) * Cz + h * Dd + c4);
        *(float4*)&smf[AQS + r * 68 + c4] = qv;
    }
    if (tid < 128) { smf[AMS + tid] = -1e30f; smf[ALS + tid] = 0.f; }

    auto load_K = [&](int k0) {
        #pragma unroll
        for (int i = 0; i < 8; i++) {
            int idx = i * 256 + tid;
            int r = idx >> 4, c4 = (idx & 15) * 4;
            cp_async16(sb + (AKS + r * 68 + c4) * 4,
                       Kp + ((size_t)(b * Tz + k0 + r)) * Cz + h * Dd + c4);
        }
        cp_commit();
    };
    auto load_V = [&](int k0) {
        #pragma unroll
        for (int i = 0; i < 8; i++) {
            int idx = i * 256 + tid;
            int r = idx >> 4, c4 = (idx & 15) * 4;
            cp_async16(sb + (AVS + r * 64 + c4) * 4,
                       Vp + ((size_t)(b * Tz + k0 + r)) * Cz + h * Dd + c4);
        }
        cp_commit();
    };

    load_K(0);
    load_V(0);
    __syncthreads();

    const int NBLK = Tz / 128;   // 16
    for (int blk = 0; blk < NBLK; blk++) {
        int k0 = blk * 128;
        cp_wait<1>();
        __syncthreads();

        // ---- S = Q @ K^T ----
        {
            wmma::fragment<wmma::accumulator, 16, 16, 8, float> acc[4][2];
            #pragma unroll
            for (int mi = 0; mi < 4; mi++)
                #pragma unroll
                for (int ni = 0; ni < 2; ni++)
                    wmma::fill_fragment(acc[mi][ni], 0.0f);
            #pragma unroll
            for (int kk = 0; kk < 8; kk++) {
                wmma::fragment<wmma::matrix_a, 16, 16, 8, wmma::precision::tf32, wmma::row_major> af[4];
                wmma::fragment<wmma::matrix_b, 16, 16, 8, wmma::precision::tf32, wmma::col_major> bf[2];
                #pragma unroll
                for (int mi = 0; mi < 4; mi++)
                    wmma::load_matrix_sync(af[mi], smf + AQS + (wm * 64 + mi * 16) * 68 + kk * 8, 68);
                #pragma unroll
                for (int ni = 0; ni < 2; ni++)
                    wmma::load_matrix_sync(bf[ni], smf + AKS + (wn * 32 + ni * 16) * 68 + kk * 8, 68);
                #pragma unroll
                for (int mi = 0; mi < 4; mi++)
                    #pragma unroll
                    for (int ni = 0; ni < 2; ni++)
                        wmma::mma_sync(acc[mi][ni], af[mi], bf[ni], acc[mi][ni]);
            }
            #pragma unroll
            for (int mi = 0; mi < 4; mi++)
                #pragma unroll
                for (int ni = 0; ni < 2; ni++)
                    wmma::store_matrix_sync(smf + ASS + (wm * 64 + mi * 16) * 132 + wn * 32 + ni * 16,
                                            acc[mi][ni], 132, wmma::mem_row_major);
        }
        __syncthreads();

        if (blk + 1 < NBLK) load_K(k0 + 128);

        // ---- online softmax ----
        {
            int r = tid >> 1, c0 = (tid & 1) * 64;
            size_t mb_idx = (((size_t)(b * Tz + qrow0 + r)) * Tz + k0 + c0) >> 5;
            uint32_t w0 = mbits[mb_idx], w1 = mbits[mb_idx + 1];
            uint64_t mw = (uint64_t)w0 | ((uint64_t)w1 << 32);
            float* Srow = smf + ASS + r * 132 + c0;
            float vmax = -1e30f;
            #pragma unroll
            for (int j = 0; j < 64; j++) {
                float s = Srow[j];
                s = ((mw >> j) & 1ull) ? s * sc : -1e30f;
                Srow[j] = s;
                vmax = fmaxf(vmax, s);
            }
            vmax = fmaxf(vmax, __shfl_xor_sync(0xffffffffu, vmax, 1));
            float mold = smf[AMS + r];
            float mnew = fmaxf(mold, vmax);
            float corr = __expf(mold - mnew);
            float lsum = 0.f;
            #pragma unroll
            for (int j = 0; j < 64; j++) {
                float p = __expf(Srow[j] - mnew);
                lsum += p;
                Srow[j] = to_tf32(p);
            }
            lsum += __shfl_xor_sync(0xffffffffu, lsum, 1);
            if ((tid & 1) == 0) {
                smf[AMS + r] = mnew;
                smf[ALS + r] = smf[ALS + r] * corr + lsum;
                smf[ACS + r] = corr;
            }
        }

        if (blk + 1 < NBLK) cp_wait<1>(); else cp_wait<0>();
        __syncthreads();

        // ---- PV = P @ V ----
        {
            wmma::fragment<wmma::accumulator, 16, 16, 8, float> acc2[4];
            #pragma unroll
            for (int mi = 0; mi < 4; mi++) wmma::fill_fragment(acc2[mi], 0.0f);
            #pragma unroll
            for (int kk = 0; kk < 16; kk++) {
                wmma::fragment<wmma::matrix_b, 16, 16, 8, wmma::precision::tf32, wmma::row_major> bf;
                wmma::load_matrix_sync(bf, smf + AVS + (kk * 8) * 64 + wn * 16, 64);
                #pragma unroll
                for (int mi = 0; mi < 4; mi++) {
                    wmma::fragment<wmma::matrix_a, 16, 16, 8, wmma::precision::tf32, wmma::row_major> af;
                    wmma::load_matrix_sync(af, smf + ASS + (wm * 64 + mi * 16) * 132 + kk * 8, 132);
                    wmma::mma_sync(acc2[mi], af, bf, acc2[mi]);
                }
            }
            __syncthreads();
            #pragma unroll
            for (int mi = 0; mi < 4; mi++)
                wmma::store_matrix_sync(smf + ASS + (wm * 64 + mi * 16) * 132 + wn * 16,
                                        acc2[mi], 132, wmma::mem_row_major);
        }

        if (blk + 1 < NBLK) load_V(k0 + 128);
        __syncthreads();

        // ---- merge into O ----
        if (blk == 0) {
            #pragma unroll
            for (int i = 0; i < 32; i++) {
                int idx = i * 256 + tid;
                int r = idx >> 6, c = idx & 63;
                smf[AOS + r * 68 + c] = smf[ASS + r * 132 + c];
            }
        } else {
            #pragma unroll
            for (int i = 0; i < 32; i++) {
                int idx = i * 256 + tid;
                int r = idx >> 6, c = idx & 63;
                smf[AOS + r * 68 + c] = smf[AOS + r * 68 + c] * smf[ACS + r] + smf[ASS + r * 132 + c];
            }
        }
        __syncthreads();
    }

    #pragma unroll
    for (int i = 0; i < 32; i++) {
        int idx = i * 256 + tid;
        int r = idx >> 6, c = idx & 63;
        float val = smf[AOS + r * 68 + c] / smf[ALS + r];
        O[((size_t)(b * Tz + qrow0 + r)) * Cz + h * Dd + c] = to_tf32(val);
    }
}

// ---------------- residual + LayerNorm epilogue ----------------
__global__ __launch_bounds__(256) void resid_ln_kernel(
    const float* __restrict__ x, const float* __restrict__ p,
    const float* __restrict__ g, const float* __restrict__ beta,
    float* __restrict__ out)
{
    const int row = blockIdx.x;
    const float* xr = x + (size_t)row * Cz;
    const float* pr = p + (size_t)row * Cz;
    float v[4];
    float s = 0.f;
    #pragma unroll
    for (int i = 0; i < 4; i++) {
        int c = threadIdx.x + i * 256;
        v[i] = xr[c] + pr[c];
        s += v[i];
    }
    float mean = blockReduceSum(s) * (1.0f / Cz);
    float s2 = 0.f;
    #pragma unroll
    for (int i = 0; i < 4; i++) { float d = v[i] - mean; s2 += d * d; }
    float var = blockReduceSum(s2) * (1.0f / Cz);
    float rstd = rsqrtf(var + 1e-5f);
    #pragma unroll
    for (int i = 0; i < 4; i++) {
        int c = threadIdx.x + i * 256;
        out[(size_t)row * Cz + c] = (v[i] - mean) * rstd * g[c] + beta[c];
    }
}

// ---------------- launch ----------------
extern "C" void kernel_launch(void* const* d_in, const int* in_sizes, int n_in,
                              void* d_out, int out_size)
{
    const float* x      = (const float*)d_in[0];
    const int*   amask  = (const int*)  d_in[1];
    const float* imp_w1 = (const float*)d_in[2];
    const float* imp_b1 = (const float*)d_in[3];
    const float* imp_g  = (const float*)d_in[4];
    const float* imp_be = (const float*)d_in[5];
    const float* imp_w2 = (const float*)d_in[6];
    const float* imp_b2 = (const float*)d_in[7];
    const float* rsn_w1 = (const float*)d_in[8];
    const float* rsn_b1 = (const float*)d_in[9];
    const float* rsn_g  = (const float*)d_in[10];
    const float* rsn_be = (const float*)d_in[11];
    const float* rsn_w2 = (const float*)d_in[12];
    const float* rsn_b2 = (const float*)d_in[13];
    const float* q_w    = (const float*)d_in[14];
    const float* q_b    = (const float*)d_in[15];
    const float* k_w    = (const float*)d_in[16];
    const float* k_b    = (const float*)d_in[17];
    const float* v_w    = (const float*)d_in[18];
    const float* v_b    = (const float*)d_in[19];
    const float* o_w    = (const float*)d_in[20];
    const float* o_b    = (const float*)d_in[21];
    const float* tmp_w1 = (const float*)d_in[22];
    const float* tmp_b1 = (const float*)d_in[23];
    const float* tmp_g  = (const float*)d_in[24];
    const float* tmp_be = (const float*)d_in[25];
    const float* tmp_w2 = (const float*)d_in[26];
    const float* tmp_b2 = (const float*)d_in[27];
    const float* norm_g = (const float*)d_in[28];
    const float* norm_b = (const float*)d_in[29];
    float* out = (float*)d_out;

    float *Himp, *xi, *Hrsn, *reasoned, *Q, *K, *V, *attn, *proj, *part, *rmean, *temp, *xr;
    float *WtImp, *WtRsn1, *WtRsn2, *WtQ, *WtK, *WtV, *WtO;
    uint32_t* mbits;
    cudaGetSymbolAddress((void**)&Himp,     g_Himp);
    cudaGetSymbolAddress((void**)&xi,       g_xi);
    cudaGetSymbolAddress((void**)&Hrsn,     g_Hrsn);
    cudaGetSymbolAddress((void**)&reasoned, g_reasoned);
    cudaGetSymbolAddress((void**)&Q,        g_Q);
    cudaGetSymbolAddress((void**)&K,        g_K);
    cudaGetSymbolAddress((void**)&V,        g_V);
    cudaGetSymbolAddress((void**)&attn,     g_attn);
    cudaGetSymbolAddress((void**)&proj,     g_proj);
    cudaGetSymbolAddress((void**)&part,     g_part);
    cudaGetSymbolAddress((void**)&rmean,    g_rmean);
    cudaGetSymbolAddress((void**)&temp,     g_temp);
    cudaGetSymbolAddress((void**)&xr,       g_xr);
    cudaGetSymbolAddress((void**)&mbits,    g_mbits);
    cudaGetSymbolAddress((void**)&WtImp,    g_WtImp);
    cudaGetSymbolAddress((void**)&WtRsn1,   g_WtRsn1);
    cudaGetSymbolAddress((void**)&WtRsn2,   g_WtRsn2);
    cudaGetSymbolAddress((void**)&WtQ,      g_WtQ);
    cudaGetSymbolAddress((void**)&WtK,      g_WtK);
    cudaGetSymbolAddress((void**)&WtV,      g_WtV);
    cudaGetSymbolAddress((void**)&WtO,      g_WtO);

    cudaFuncSetAttribute(gemm_tf32, cudaFuncAttributeMaxDynamicSharedMemorySize, GSMEM_BYTES);
    cudaFuncSetAttribute(gemm_tf32_qkv, cudaFuncAttributeMaxDynamicSharedMemorySize, GSMEM_BYTES);
    cudaFuncSetAttribute(flash_wmma_kernel, cudaFuncAttributeMaxDynamicSharedMemorySize, ASM_BYTES);

    // batched weight transposes (+ tf32 rounding)
    TransArgs ta;
    ta.src[0] = imp_w1; ta.dst[0] = WtImp;  ta.n[0] = CH;
    ta.src[1] = rsn_w1; ta.dst[1] = WtRsn1; ta.n[1] = Cz;
    ta.src[2] = rsn_w2; ta.dst[2] = WtRsn2; ta.n[2] = Cz;
    ta.src[3] = q_w;    ta.dst[3] = WtQ;    ta.n[3] = Cz;
    ta.src[4] = k_w;    ta.dst[4] = WtK;    ta.n[4] = Cz;
    ta.src[5] = v_w;    ta.dst[5] = WtV;    ta.n[5] = Cz;
    ta.src[6] = o_w;    ta.dst[6] = WtO;    ta.n[6] = Cz;
    transpose_round_batch<<<dim3(32, 32, 7), dim3(32, 8)>>>(ta);
    round_tf32_kernel<<<NT*Cz/256, 256>>>(x, xr);
    pack_mask_kernel<<<(int)((size_t)Bz*Tz*Tz/256), 256>>>(amask, mbits);

    // 1. importance net first linear
    gemm_tf32<<<dim3(CH/128, NT/128), 256, GSMEM_BYTES>>>(xr, WtImp, imp_b1, Himp, CH, 0);
    // 2. LN + GELU
    ln_gelu_kernel<CH><<<NT, 256>>>(Himp, imp_g, imp_be);
    // 3. gate
    gate_xi_kernel<<<NT, 256>>>(Himp, imp_w2, imp_b2, x, xi);
    // 4. reasoning first linear
    gemm_tf32<<<dim3(Cz/128, NT/128), 256, GSMEM_BYTES>>>(xi, WtRsn1, rsn_b1, Hrsn, Cz, 0);
    // 5. LN + GELU
    ln_gelu_kernel<Cz><<<NT, 256>>>(Hrsn, rsn_g, rsn_be);
    // 6. reasoning second linear (rounded: feeds q-proj)
    gemm_tf32<<<dim3(Cz/128, NT/128), 256, GSMEM_BYTES>>>(Hrsn, WtRsn2, rsn_b2, reasoned, Cz, 1);
    // 7. Q/K/V projections batched (rounded: feed wmma attention)
    gemm_tf32_qkv<<<dim3(Cz/128, NT/128, 3), 256, GSMEM_BYTES>>>(
        reasoned, xi, xr, WtQ, WtK, WtV, q_b, k_b, v_b, Q, K, V);
    // 8. column mean
    colmean_part<<<dim3(Cz/256, Bz, 8), 256>>>(reasoned, part);
    colmean_fin<<<dim3(Cz/256, Bz), 256>>>(part, rmean);
    // 9. temperature net
    temp_kernel<<<Bz, 512>>>(rmean, tmp_w1, tmp_b1, tmp_g, tmp_be, tmp_w2, tmp_b2, temp);
    // 10. attention (wmma tf32)
    flash_wmma_kernel<<<dim3(Tz/128, Hh, Bz), 256, ASM_BYTES>>>(Q, K, V, mbits, temp, attn);
    // 11. output projection
    gemm_tf32<<<dim3(Cz/128, NT/128), 256, GSMEM_BYTES>>>(attn, WtO, o_b, proj, Cz, 0);
    // 12. residual + LN
    resid_ln_kernel<<<NT, 256>>>(x, proj, norm_g, norm_b, out);
}